// round 11
// baseline (speedup 1.0000x reference)
#include <cuda_runtime.h>
#include <cuda_fp16.h>
#include <cstdint>

#define NN    1024
#define DDIM  512
#define HDIM  150
#define HP    160
#define WWIN  250
#define OUTW  251
#define NTHR  256

// ---- dynamic SMEM byte offsets (main kernel) ----
// Stage1: A[buf][sub]: SA + buf*18432 + sub*9216   (0..36864)
//         B[buf]:      SB + buf*21888              (36864..80640)
// Stage2: W2 tile at SW2 (=B buf0 slot), h1 at SH1 + sub*27648 + t2*9216
#define SA    0
#define SB    36864
#define SW2   36864
#define SH1   58752
#define SRED  114048
#define SMEM_TOTAL 114560

#define BROWS 152
#define TILE_B_BYTES (BROWS * 144)      // 21888
#define TILE_B_U4    (TILE_B_BYTES/16)  // 1368
#define TILE_W_HALVES (BROWS * 72)      // 10944

// ---------------------------------------------------------------------------
// Device scratch
// ---------------------------------------------------------------------------
__device__ float g_giT[NN * HP];      // g@W1a + b1, [i][h], zero pad h>=150
__device__ float g_gjT_T[HP * NN];    // (g@W1b)^T, [h][i], zero pad
__device__ __align__(16) __half g_h[NN * DDIM];   // fp16 copy of g
__device__ __align__(16) __half g_W1hi[8 * TILE_W_HALVES];
__device__ __align__(16) __half g_W2hi[3 * TILE_W_HALVES];

// ---------------------------------------------------------------------------
// Helpers
// ---------------------------------------------------------------------------
__device__ __forceinline__ uint32_t smem_u32(const void* p) {
    uint32_t a;
    asm("{ .reg .u64 t; cvta.to.shared.u64 t, %1; cvt.u32.u64 %0, t; }"
        : "=r"(a) : "l"(p));
    return a;
}

__device__ __forceinline__ void cp16(uint32_t s, const void* g) {
    asm volatile("{\n\t.reg .u64 gp;\n\tcvta.to.global.u64 gp, %1;\n\t"
                 "cp.async.cg.shared.global [%0], [gp], 16;\n\t}"
                 :: "r"(s), "l"(g) : "memory");
}
#define CP_COMMIT() asm volatile("cp.async.commit_group;" ::: "memory")
#define CP_WAIT0()  asm volatile("cp.async.wait_group 0;" ::: "memory")

__device__ __forceinline__ void ldsm4(uint32_t* r, uint32_t addr) {
    asm volatile("ldmatrix.sync.aligned.m8n8.x4.shared.b16 {%0,%1,%2,%3}, [%4];"
        : "=r"(r[0]), "=r"(r[1]), "=r"(r[2]), "=r"(r[3]) : "r"(addr));
}

__device__ __forceinline__ void mma16816(float* c,
    uint32_t a0, uint32_t a1, uint32_t a2, uint32_t a3,
    uint32_t b0, uint32_t b1)
{
    asm volatile(
        "mma.sync.aligned.m16n8k16.row.col.f32.f16.f16.f32 "
        "{%0,%1,%2,%3}, {%4,%5,%6,%7}, {%8,%9}, {%0,%1,%2,%3};"
        : "+f"(c[0]), "+f"(c[1]), "+f"(c[2]), "+f"(c[3])
        : "r"(a0), "r"(a1), "r"(a2), "r"(a3), "r"(b0), "r"(b1));
}

__device__ __forceinline__ uint4 hmul_u4(uint4 x, uint4 y) {
    __half2* xa = (__half2*)&x;
    __half2* ya = (__half2*)&y;
    uint4 r;
    __half2* ra = (__half2*)&r;
    ra[0] = __hmul2(xa[0], ya[0]);
    ra[1] = __hmul2(xa[1], ya[1]);
    ra[2] = __hmul2(xa[2], ya[2]);
    ra[3] = __hmul2(xa[3], ya[3]);
    return r;
}

// ---------------------------------------------------------------------------
// Merged precompute (unchanged from R10).
// ---------------------------------------------------------------------------
__global__ void __launch_bounds__(640) precompute_all(
    const float* __restrict__ g, const float* __restrict__ W1,
    const float* __restrict__ b1, const float* __restrict__ W2)
{
    const int tid = threadIdx.x;

    if (blockIdx.x >= 256) {
        const int bt = blockIdx.x - 256;
        const float* W1c = W1 + 2 * DDIM * HDIM;
        if (bt < 8) {
            __half* dhi = g_W1hi + bt * TILE_W_HALVES;
            for (int idx = tid; idx < BROWS * 64; idx += 640) {
                int n = idx >> 6, k = idx & 63;
                int d = bt * 64 + k;
                float val = (n < HDIM) ? W1c[d * HDIM + n] : 0.f;
                dhi[n * 72 + k] = __float2half_rn(val);
            }
        } else {
            const int kt = bt - 8;
            __half* dhi = g_W2hi + kt * TILE_W_HALVES;
            for (int idx = tid; idx < BROWS * 64; idx += 640) {
                int n = idx >> 6, k = idx & 63;
                int kg = kt * 64 + k;
                float val = (kg < HDIM && n < HDIM) ? W2[kg * HDIM + n] : 0.f;
                dhi[n * 72 + k] = __float2half_rn(val);
            }
        }
        return;
    }

    __shared__ float gs[4 * DDIM];
    __shared__ float red[3 * 160 * 8];
    const int i0 = blockIdx.x * 4;
    {
        const float4* src = (const float4*)(g + i0 * DDIM);
        float4* dst = (float4*)gs;
        for (int x = tid; x < (4 * DDIM) / 4; x += 640) dst[x] = src[x];
    }
    __syncthreads();
    for (int x = tid; x < 4 * DDIM; x += 640)
        g_h[i0 * DDIM + x] = __float2half_rn(gs[x]);

    const int h  = tid % 160;
    const int ks = tid / 160;
    const bool hv = (h < HDIM);
    const int hc = hv ? h : 0;
    float acc1[4], acc2[4];
    float bb = (hv && ks == 0) ? b1[h] : 0.f;
    #pragma unroll
    for (int q = 0; q < 4; ++q) { acc1[q] = bb; acc2[q] = 0.f; }
    const float* W1a = W1 + hc;
    const float* W1b = W1 + DDIM * HDIM + hc;
    const int d0b = ks * 128;
    for (int d0 = d0b; d0 < d0b + 128; d0 += 8) {
        float w1r[8], w2r[8];
        #pragma unroll
        for (int u = 0; u < 8; ++u) {
            w1r[u] = W1a[(d0 + u) * HDIM];
            w2r[u] = W1b[(d0 + u) * HDIM];
        }
        if (!hv) {
            #pragma unroll
            for (int u = 0; u < 8; ++u) { w1r[u] = 0.f; w2r[u] = 0.f; }
        }
        #pragma unroll
        for (int q = 0; q < 4; ++q) {
            const float* gq = gs + q * DDIM + d0;
            float4 ga = *(const float4*)gq;
            float4 gb = *(const float4*)(gq + 4);
            acc1[q] += ga.x * w1r[0] + ga.y * w1r[1] + ga.z * w1r[2] + ga.w * w1r[3]
                     + gb.x * w1r[4] + gb.y * w1r[5] + gb.z * w1r[6] + gb.w * w1r[7];
            acc2[q] += ga.x * w2r[0] + ga.y * w2r[1] + ga.z * w2r[2] + ga.w * w2r[3]
                     + gb.x * w2r[4] + gb.y * w2r[5] + gb.z * w2r[6] + gb.w * w2r[7];
        }
    }
    if (ks > 0) {
        float* r = red + ((ks - 1) * 160 + h) * 8;
        #pragma unroll
        for (int q = 0; q < 4; ++q) { r[q] = acc1[q]; r[4 + q] = acc2[q]; }
    }
    __syncthreads();
    if (ks == 0) {
        #pragma unroll
        for (int s = 0; s < 3; ++s) {
            const float* r = red + (s * 160 + h) * 8;
            #pragma unroll
            for (int q = 0; q < 4; ++q) { acc1[q] += r[q]; acc2[q] += r[4 + q]; }
        }
        #pragma unroll
        for (int q = 0; q < 4; ++q) {
            g_giT[(i0 + q) * HP + h]   = acc1[q];
            g_gjT_T[h * NN + (i0 + q)] = acc2[q];
        }
    }
}

// ---------------------------------------------------------------------------
// Main kernel. CTA = (i, 128 pairs = 2 subs of 64). grid (2, 1024), 256 thr.
// 8 warps: sub=wid>>2, wm=wid&1, wn=(wid>>1)&1. A+B fully double-buffered,
// ONE sync per k-tile. B tiles loaded once serve both subs.
// ---------------------------------------------------------------------------
__global__ void __launch_bounds__(NTHR, 2) pair_mma_kernel(
    const float* __restrict__ sm, const float* __restrict__ b2,
    const float* __restrict__ W3, const float* __restrict__ b3,
    float* __restrict__ out)
{
    extern __shared__ char smem[];
    const uint32_t sb = smem_u32(smem);
    const int tid = threadIdx.x;
    const int i  = blockIdx.y;
    const int kb = blockIdx.x * 128;

    // ---- early exit: whole CTA out of window ----
    if (i - WWIN + kb + 127 < 0) {
        if (tid < 128) out[(size_t)i * OUTW + kb + tid] = 0.f;
        return;
    }

    const int wid = tid >> 5, lid = tid & 31;
    const int sub = wid >> 2, wq = wid & 3;
    const int wm = wq & 1, wn = wq >> 1;
    const int gq = lid >> 2, t = lid & 3;
    const bool trim = (wn == 1);
    const int k0 = kb + sub * 64;
    const uint32_t subA = (uint32_t)(sub * 9216);

    int jrow[2][2];
    #pragma unroll
    for (int mi = 0; mi < 2; ++mi)
        #pragma unroll
        for (int h8 = 0; h8 < 2; ++h8) {
            int p = wm * 32 + mi * 16 + gq + h8 * 8;
            int j = i - WWIN + k0 + p;
            jrow[mi][h8] = min(max(j, 0), NN - 1);
        }

    // ---- accumulators, init with bias terms giT[i][col] + gjT[col][j] ----
    float acc[2][10][4];
    {
        const float* giR = g_giT + i * HP;
        #pragma unroll
        for (int nt = 0; nt < 10; ++nt)
            #pragma unroll
            for (int par = 0; par < 2; ++par) {
                int col = wn * 80 + nt * 8 + 2 * t + par;
                float gic = giR[col];
                const float* gjc = g_gjT_T + col * NN;
                #pragma unroll
                for (int mi = 0; mi < 2; ++mi)
                    #pragma unroll
                    for (int h8 = 0; h8 < 2; ++h8)
                        acc[mi][nt][h8 * 2 + par] = gic + gjc[jrow[mi][h8]];
            }
    }

    // ---- ldmatrix lane offsets (within sub's 64-row A / shared B) ----
    const int mq = lid >> 3, rr = lid & 7;
    uint32_t aOff[2], bOff[5];
    #pragma unroll
    for (int mi = 0; mi < 2; ++mi)
        aOff[mi] = (uint32_t)((wm * 32 + mi * 16 + (mq & 1) * 8 + rr) * 144 + (mq >> 1) * 16);
    #pragma unroll
    for (int ntp = 0; ntp < 5; ++ntp) {
        int rowb = wn * 80 + (ntp * 2 + (mq >> 1)) * 8 + rr;
        if (rowb > 151) rowb = 151;           // clamp dead tile-19 rows (values unused)
        bOff[ntp] = (uint32_t)(rowb * 144 + (mq & 1) * 16);
    }

    // ---- A-prep identity: 4 rounds of 32 rows x 8 chunks (128 rows) ----
    const int c8 = tid & 7;            // 16B chunk within 128B k-slab
    const int rA = tid >> 3;           // 0..31
    const __half* giBase = g_h + (size_t)i * DDIM;
    int jr[4];
    uint32_t aDstOff[4];
    #pragma unroll
    for (int rd = 0; rd < 4; ++rd) {
        int p = rd * 32 + rA;
        jr[rd] = min(max(i - WWIN + kb + p, 0), NN - 1);
        aDstOff[rd] = (uint32_t)((p >> 6) * 9216 + (p & 63) * 144 + c8 * 16);
    }

    // =================== Stage 1: acc += (gi*gj) @ W1c (fp16) ==============
    // Prolog: B(0) + A(0) into buf 0
    {
        const char* src = (const char*)g_W1hi;
        for (int x = tid; x < TILE_B_U4; x += NTHR)
            cp16(sb + SB + x * 16, src + x * 16);
        CP_COMMIT();
        const uint4 gi16 = ((const uint4*)giBase)[c8];
        #pragma unroll
        for (int rd = 0; rd < 4; ++rd) {
            uint4 gj16 = ((const uint4*)(g_h + (size_t)jr[rd] * DDIM))[c8];
            *(uint4*)(smem + SA + aDstOff[rd]) = hmul_u4(gi16, gj16);
        }
        CP_WAIT0();
        __syncthreads();
    }

    for (int kt = 0; kt < 8; ++kt) {
        // issue next B (or W2 tile-0 prefetch into the dead B0 slot)
        if (kt < 7) {
            const char* src = (const char*)(g_W1hi + (kt + 1) * TILE_W_HALVES);
            uint32_t dstB = sb + SB + (uint32_t)(((kt + 1) & 1) * 21888);
            for (int x = tid; x < TILE_B_U4; x += NTHR)
                cp16(dstB + x * 16, src + x * 16);
        } else {
            const char* src = (const char*)g_W2hi;   // kt=7 reads B[1]; B[0] slot dead
            for (int x = tid; x < TILE_B_U4; x += NTHR)
                cp16(sb + SW2 + x * 16, src + x * 16);
        }
        CP_COMMIT();

        // MMA(kt)
        const uint32_t aB = sb + SA + (uint32_t)((kt & 1) * 18432) + subA;
        const uint32_t bB = sb + SB + (uint32_t)((kt & 1) * 21888);
        #pragma unroll
        for (int ks = 0; ks < 4; ++ks) {
            uint32_t ah0[4], ah1[4];
            ldsm4(ah0, aB + aOff[0] + ks * 32);
            ldsm4(ah1, aB + aOff[1] + ks * 32);
            #pragma unroll
            for (int ntp = 0; ntp < 5; ++ntp) {
                uint32_t bf[4];
                ldsm4(bf, bB + bOff[ntp] + ks * 32);
                mma16816(acc[0][2 * ntp],     ah0[0], ah0[1], ah0[2], ah0[3], bf[0], bf[1]);
                mma16816(acc[1][2 * ntp],     ah1[0], ah1[1], ah1[2], ah1[3], bf[0], bf[1]);
                if (ntp < 4 || !trim) {
                    mma16816(acc[0][2 * ntp + 1], ah0[0], ah0[1], ah0[2], ah0[3], bf[2], bf[3]);
                    mma16816(acc[1][2 * ntp + 1], ah1[0], ah1[1], ah1[2], ah1[3], bf[2], bf[3]);
                }
            }
        }

        // A-prep(kt+1) into the other A buffer (readers of it synced last iter)
        if (kt < 7) {
            const uint4 gi16 = ((const uint4*)(giBase + (kt + 1) * 64))[c8];
            uint32_t aD = (uint32_t)(((kt + 1) & 1) * 18432);
            #pragma unroll
            for (int rd = 0; rd < 4; ++rd) {
                uint4 gj16 = ((const uint4*)(g_h + (size_t)jr[rd] * DDIM + (kt + 1) * 64))[c8];
                *(uint4*)(smem + SA + aD + aDstOff[rd]) = hmul_u4(gi16, gj16);
            }
        }
        CP_WAIT0();
        __syncthreads();      // ONE sync per k-tile
    }

    // ============ h1 = relu(acc) -> SMEM (single fp16, per-sub tiles) ======
    {
        const uint32_t hBase = SH1 + (uint32_t)(sub * 27648);
        #pragma unroll
        for (int mi = 0; mi < 2; ++mi)
            #pragma unroll
            for (int h8 = 0; h8 < 2; ++h8) {
                int row = wm * 32 + mi * 16 + gq + h8 * 8;
                #pragma unroll
                for (int nt = 0; nt < 10; ++nt) {
                    int col = wn * 80 + nt * 8 + 2 * t;
                    float v0 = fmaxf(acc[mi][nt][h8 * 2 + 0], 0.f);
                    float v1 = fmaxf(acc[mi][nt][h8 * 2 + 1], 0.f);
                    __half2 h = __float22half2_rn(make_float2(v0, v1));
                    int tile = col >> 6;
                    uint32_t off = hBase + (uint32_t)(tile * 9216 + row * 144 + (col & 63) * 2);
                    *(uint32_t*)(smem + off) = *(uint32_t*)&h;
                }
            }
    }

    // ---- re-init acc with b2 for stage 2 ----
    #pragma unroll
    for (int nt = 0; nt < 10; ++nt)
        #pragma unroll
        for (int par = 0; par < 2; ++par) {
            int col = wn * 80 + nt * 8 + 2 * t + par;
            float bv = (col < HDIM) ? b2[col] : 0.f;
            #pragma unroll
            for (int mi = 0; mi < 2; ++mi)
                #pragma unroll
                for (int h8 = 0; h8 < 2; ++h8)
                    acc[mi][nt][h8 * 2 + par] = bv;
        }
    __syncthreads();          // h1 visible; W2(0) already waited at kt=7

    // ======== Stage 2: acc += relu(h1) @ W2 (fp16, K=160) ==================
    for (int kt2 = 0; kt2 < 3; ++kt2) {
        if (kt2 > 0) {
            const char* src = (const char*)(g_W2hi + kt2 * TILE_W_HALVES);
            for (int x = tid; x < TILE_B_U4; x += NTHR)
                cp16(sb + SW2 + x * 16, src + x * 16);
            CP_COMMIT();
            CP_WAIT0();
            __syncthreads();
        }
        const uint32_t aB2 = sb + SH1 + (uint32_t)(sub * 27648 + kt2 * 9216);
        const int nks = (kt2 == 2) ? 2 : 4;
        for (int ks = 0; ks < nks; ++ks) {
            uint32_t af0[4], af1[4];
            ldsm4(af0, aB2 + aOff[0] + ks * 32);
            ldsm4(af1, aB2 + aOff[1] + ks * 32);
            #pragma unroll
            for (int ntp = 0; ntp < 5; ++ntp) {
                uint32_t bf[4];
                ldsm4(bf, sb + SW2 + bOff[ntp] + ks * 32);
                mma16816(acc[0][2 * ntp],     af0[0], af0[1], af0[2], af0[3], bf[0], bf[1]);
                mma16816(acc[1][2 * ntp],     af1[0], af1[1], af1[2], af1[3], bf[0], bf[1]);
                if (ntp < 4 || !trim) {
                    mma16816(acc[0][2 * ntp + 1], af0[0], af0[1], af0[2], af0[3], bf[2], bf[3]);
                    mma16816(acc[1][2 * ntp + 1], af1[0], af1[1], af1[2], af1[3], bf[2], bf[3]);
                }
            }
        }
        __syncthreads();
    }

    // =================== Epilogue: relu(acc) @ W3, reduce ==================
    float rsum[2][2] = {{0.f, 0.f}, {0.f, 0.f}};
    #pragma unroll
    for (int nt = 0; nt < 10; ++nt)
        #pragma unroll
        for (int par = 0; par < 2; ++par) {
            int col = wn * 80 + nt * 8 + 2 * t + par;
            float w3 = (col < HDIM) ? W3[col] : 0.f;
            #pragma unroll
            for (int mi = 0; mi < 2; ++mi)
                #pragma unroll
                for (int h8 = 0; h8 < 2; ++h8)
                    rsum[mi][h8] += fmaxf(acc[mi][nt][h8 * 2 + par], 0.f) * w3;
        }
    #pragma unroll
    for (int mi = 0; mi < 2; ++mi)
        #pragma unroll
        for (int h8 = 0; h8 < 2; ++h8) {
            float v = rsum[mi][h8];
            v += __shfl_xor_sync(0xffffffffu, v, 1);
            v += __shfl_xor_sync(0xffffffffu, v, 2);
            rsum[mi][h8] = v;
        }

    float* sred = (float*)(smem + SRED + sub * 256);
    if (wn == 0 && t == 0) {
        #pragma unroll
        for (int mi = 0; mi < 2; ++mi)
            #pragma unroll
            for (int h8 = 0; h8 < 2; ++h8)
                sred[wm * 32 + mi * 16 + gq + h8 * 8] = rsum[mi][h8];
    }
    __syncthreads();
    if (wn == 1 && t == 0) {
        float smi = sm[i];
        float bb3 = b3[0];
        #pragma unroll
        for (int mi = 0; mi < 2; ++mi)
            #pragma unroll
            for (int h8 = 0; h8 < 2; ++h8) {
                int p = wm * 32 + mi * 16 + gq + h8 * 8;
                int k = k0 + p;
                int j = i - WWIN + k;
                float tot = rsum[mi][h8] + sred[p];
                if (k < WWIN) {
                    float val = 0.f;
                    if (j >= 0) val = tot + bb3 + smi + sm[j];
                    out[(size_t)i * OUTW + k] = val;
                } else if (k == WWIN) {
                    out[(size_t)i * OUTW + k] = 0.f;   // epsilon column
                }
            }
    }
}

// ---------------------------------------------------------------------------
extern "C" void kernel_launch(void* const* d_in, const int* in_sizes, int n_in,
                              void* d_out, int out_size)
{
    const float* g  = (const float*)d_in[0];
    const float* sm = (const float*)d_in[1];
    const float* W1 = (const float*)d_in[2];
    const float* b1 = (const float*)d_in[3];
    const float* W2 = (const float*)d_in[4];
    const float* b2 = (const float*)d_in[5];
    const float* W3 = (const float*)d_in[6];
    const float* b3 = (const float*)d_in[7];
    float* out = (float*)d_out;

    cudaFuncSetAttribute(pair_mma_kernel,
                         cudaFuncAttributeMaxDynamicSharedMemorySize, SMEM_TOTAL);

    precompute_all<<<267, 640>>>(g, W1, b1, W2);

    dim3 grid(2, NN);
    pair_mma_kernel<<<grid, NTHR, SMEM_TOTAL>>>(sm, b2, W3, b3, out);
}

// round 12
// speedup vs baseline: 1.0341x; 1.0341x over previous
#include <cuda_runtime.h>
#include <cuda_fp16.h>
#include <cstdint>

#define NN    1024
#define DDIM  512
#define HDIM  150
#define HP    160
#define WWIN  250
#define OUTW  251
#define NTHR  128
#define MT    64

// ---- dynamic SMEM byte offsets (main kernel), all tiles pitch-128 SW128 ----
// A[buf] = SA + buf*8192 (64 rows). B[buf] = SB + buf*19456 (152 rows).
// kt uses B[(kt+1)&1]; cp target for next tile = B[kt&1]; W2 t0 prefetch at kt=7
// also lands at B[1] (= same expression). Stage2: h1 tiles at SA, SA+8192, SB;
// W2 tiles stream into SW2 = B[1].
#define SA    0
#define SB    16384
#define SW2   (SB + 19456)      // 35840
#define SRED  55296
#define SMEM_TOTAL 55552

#define BROWS 152
#define TILE_B_BYTES (BROWS * 128)      // 19456
#define TILE_B_U4    (TILE_B_BYTES/16)  // 1216
#define TILE_W_HALVES (BROWS * 64)      // 9728 halves per tile

// ---------------------------------------------------------------------------
// Device scratch
// ---------------------------------------------------------------------------
__device__ float g_giT[NN * HP];      // g@W1a + b1, [i][h], zero pad h>=150
__device__ float g_gjT_T[HP * NN];    // (g@W1b)^T, [h][i], zero pad
__device__ __align__(16) __half g_h[NN * DDIM];   // fp16 copy of g
__device__ __align__(16) __half g_W1hi[8 * TILE_W_HALVES];   // SW128-swizzled
__device__ __align__(16) __half g_W2hi[3 * TILE_W_HALVES];   // SW128-swizzled

// ---------------------------------------------------------------------------
// Helpers
// ---------------------------------------------------------------------------
__device__ __forceinline__ uint32_t smem_u32(const void* p) {
    uint32_t a;
    asm("{ .reg .u64 t; cvta.to.shared.u64 t, %1; cvt.u32.u64 %0, t; }"
        : "=r"(a) : "l"(p));
    return a;
}

__device__ __forceinline__ void cp16(uint32_t s, const void* g) {
    asm volatile("{\n\t.reg .u64 gp;\n\tcvta.to.global.u64 gp, %1;\n\t"
                 "cp.async.cg.shared.global [%0], [gp], 16;\n\t}"
                 :: "r"(s), "l"(g) : "memory");
}
#define CP_COMMIT() asm volatile("cp.async.commit_group;" ::: "memory")
#define CP_WAIT0()  asm volatile("cp.async.wait_group 0;" ::: "memory")

__device__ __forceinline__ void ldsm4(uint32_t* r, uint32_t addr) {
    asm volatile("ldmatrix.sync.aligned.m8n8.x4.shared.b16 {%0,%1,%2,%3}, [%4];"
        : "=r"(r[0]), "=r"(r[1]), "=r"(r[2]), "=r"(r[3]) : "r"(addr));
}

__device__ __forceinline__ void mma16816(float* c,
    uint32_t a0, uint32_t a1, uint32_t a2, uint32_t a3,
    uint32_t b0, uint32_t b1)
{
    asm volatile(
        "mma.sync.aligned.m16n8k16.row.col.f32.f16.f16.f32 "
        "{%0,%1,%2,%3}, {%4,%5,%6,%7}, {%8,%9}, {%0,%1,%2,%3};"
        : "+f"(c[0]), "+f"(c[1]), "+f"(c[2]), "+f"(c[3])
        : "r"(a0), "r"(a1), "r"(a2), "r"(a3), "r"(b0), "r"(b1));
}

__device__ __forceinline__ uint4 hmul_u4(uint4 x, uint4 y) {
    __half2* xa = (__half2*)&x;
    __half2* ya = (__half2*)&y;
    uint4 r;
    __half2* ra = (__half2*)&r;
    ra[0] = __hmul2(xa[0], ya[0]);
    ra[1] = __hmul2(xa[1], ya[1]);
    ra[2] = __hmul2(xa[2], ya[2]);
    ra[3] = __hmul2(xa[3], ya[3]);
    return r;
}

// ---------------------------------------------------------------------------
// Merged precompute. Blocks 0..255: giT/gjT_T/g_h (4 rows each, 640 thr).
// Blocks 256..266: SW128-swizzled fp16 weight B-tiles (W1c: 8, W2: 3).
// ---------------------------------------------------------------------------
__global__ void __launch_bounds__(640) precompute_all(
    const float* __restrict__ g, const float* __restrict__ W1,
    const float* __restrict__ b1, const float* __restrict__ W2)
{
    const int tid = threadIdx.x;

    if (blockIdx.x >= 256) {
        const int bt = blockIdx.x - 256;
        const float* W1c = W1 + 2 * DDIM * HDIM;
        char* dst = (bt < 8) ? (char*)g_W1hi + bt * TILE_B_BYTES
                             : (char*)g_W2hi + (bt - 8) * TILE_B_BYTES;
        for (int idx = tid; idx < BROWS * 64; idx += 640) {
            int n = idx >> 6, k = idx & 63;
            float val;
            if (bt < 8) {
                int d = bt * 64 + k;
                val = (n < HDIM) ? W1c[d * HDIM + n] : 0.f;
            } else {
                int kg = (bt - 8) * 64 + k;
                val = (kg < HDIM && n < HDIM) ? W2[kg * HDIM + n] : 0.f;
            }
            uint32_t off = (uint32_t)(n * 128 + ((k * 2) ^ ((n & 7) << 4)));
            *(__half*)(dst + off) = __float2half_rn(val);
        }
        return;
    }

    __shared__ float gs[4 * DDIM];
    __shared__ float red[3 * 160 * 8];
    const int i0 = blockIdx.x * 4;
    {
        const float4* src = (const float4*)(g + i0 * DDIM);
        float4* dst = (float4*)gs;
        for (int x = tid; x < (4 * DDIM) / 4; x += 640) dst[x] = src[x];
    }
    __syncthreads();
    for (int x = tid; x < 4 * DDIM; x += 640)
        g_h[i0 * DDIM + x] = __float2half_rn(gs[x]);

    const int h  = tid % 160;
    const int ks = tid / 160;
    const bool hv = (h < HDIM);
    const int hc = hv ? h : 0;
    float acc1[4], acc2[4];
    float bb = (hv && ks == 0) ? b1[h] : 0.f;
    #pragma unroll
    for (int q = 0; q < 4; ++q) { acc1[q] = bb; acc2[q] = 0.f; }
    const float* W1a = W1 + hc;
    const float* W1b = W1 + DDIM * HDIM + hc;
    const int d0b = ks * 128;
    for (int d0 = d0b; d0 < d0b + 128; d0 += 8) {
        float w1r[8], w2r[8];
        #pragma unroll
        for (int u = 0; u < 8; ++u) {
            w1r[u] = W1a[(d0 + u) * HDIM];
            w2r[u] = W1b[(d0 + u) * HDIM];
        }
        if (!hv) {
            #pragma unroll
            for (int u = 0; u < 8; ++u) { w1r[u] = 0.f; w2r[u] = 0.f; }
        }
        #pragma unroll
        for (int q = 0; q < 4; ++q) {
            const float* gq = gs + q * DDIM + d0;
            float4 ga = *(const float4*)gq;
            float4 gb = *(const float4*)(gq + 4);
            acc1[q] += ga.x * w1r[0] + ga.y * w1r[1] + ga.z * w1r[2] + ga.w * w1r[3]
                     + gb.x * w1r[4] + gb.y * w1r[5] + gb.z * w1r[6] + gb.w * w1r[7];
            acc2[q] += ga.x * w2r[0] + ga.y * w2r[1] + ga.z * w2r[2] + ga.w * w2r[3]
                     + gb.x * w2r[4] + gb.y * w2r[5] + gb.z * w2r[6] + gb.w * w2r[7];
        }
    }
    if (ks > 0) {
        float* r = red + ((ks - 1) * 160 + h) * 8;
        #pragma unroll
        for (int q = 0; q < 4; ++q) { r[q] = acc1[q]; r[4 + q] = acc2[q]; }
    }
    __syncthreads();
    if (ks == 0) {
        #pragma unroll
        for (int s = 0; s < 3; ++s) {
            const float* r = red + (s * 160 + h) * 8;
            #pragma unroll
            for (int q = 0; q < 4; ++q) { acc1[q] += r[q]; acc2[q] += r[4 + q]; }
        }
        #pragma unroll
        for (int q = 0; q < 4; ++q) {
            g_giT[(i0 + q) * HP + h]   = acc1[q];
            g_gjT_T[h * NN + (i0 + q)] = acc2[q];
        }
    }
}

// ---------------------------------------------------------------------------
// Main kernel. CTA = (i, 64 pairs). grid (4, 1024), 128 thr, 4 CTAs/SM.
// SW128 tiles; A and B BOTH double-buffered -> ONE sync per k-tile.
// ---------------------------------------------------------------------------
__global__ void __launch_bounds__(NTHR, 4) pair_mma_kernel(
    const float* __restrict__ sm, const float* __restrict__ b2,
    const float* __restrict__ W3, const float* __restrict__ b3,
    float* __restrict__ out)
{
    extern __shared__ char smem[];
    const uint32_t sb = smem_u32(smem);
    const int tid = threadIdx.x;
    const int i  = blockIdx.y;
    const int k0 = blockIdx.x * MT;

    // ---- early exit: whole CTA out of window ----
    if (i - WWIN + k0 + (MT - 1) < 0) {
        if (tid < MT) out[(size_t)i * OUTW + k0 + tid] = 0.f;
        return;
    }

    const int wid = tid >> 5, lid = tid & 31;
    const int wm = wid & 1, wn = wid >> 1;
    const int gq = lid >> 2, t = lid & 3;
    const bool trim = (wn == 1);

    int jrow[2][2];
    #pragma unroll
    for (int mi = 0; mi < 2; ++mi)
        #pragma unroll
        for (int h8 = 0; h8 < 2; ++h8) {
            int p = wm * 32 + mi * 16 + gq + h8 * 8;
            int j = i - WWIN + k0 + p;
            jrow[mi][h8] = min(max(j, 0), NN - 1);
        }

    // ---- accumulators, init with bias terms giT[i][col] + gjT[col][j] ----
    float acc[2][10][4];
    {
        const float* giR = g_giT + i * HP;
        #pragma unroll
        for (int nt = 0; nt < 10; ++nt)
            #pragma unroll
            for (int par = 0; par < 2; ++par) {
                int col = wn * 80 + nt * 8 + 2 * t + par;
                float gic = giR[col];
                const float* gjc = g_gjT_T + col * NN;
                #pragma unroll
                for (int mi = 0; mi < 2; ++mi)
                    #pragma unroll
                    for (int h8 = 0; h8 < 2; ++h8)
                        acc[mi][nt][h8 * 2 + par] = gic + gjc[jrow[mi][h8]];
            }
    }

    // ---- ldmatrix lane offsets (swizzled pitch-128) ----
    const int mq = lid >> 3, rr = lid & 7;
    const uint32_t cbA = (uint32_t)((mq >> 1) * 16);
    const uint32_t cbB = (uint32_t)((mq & 1) * 16);
    uint32_t aBase[2], aXor[2], bBase[5], bXor[5];
    #pragma unroll
    for (int mi = 0; mi < 2; ++mi) {
        int row = wm * 32 + mi * 16 + (mq & 1) * 8 + rr;
        aBase[mi] = (uint32_t)(row * 128);
        aXor[mi]  = (uint32_t)((row & 7) << 4);
    }
    #pragma unroll
    for (int ntp = 0; ntp < 5; ++ntp) {
        int rowb = wn * 80 + (ntp * 2 + (mq >> 1)) * 8 + rr;
        if (rowb > 151) rowb = 151;           // clamp dead tile-19 rows (values unused)
        bBase[ntp] = (uint32_t)(rowb * 128);
        bXor[ntp]  = (uint32_t)((rowb & 7) << 4);
    }

    // ---- A-prep identity (coalesced, swizzled dst) ----
    const int c8 = tid & 7;            // 16B chunk within 128B k-slab
    const int rA = tid >> 3;           // 0..15
    const __half* giBase = g_h + (size_t)i * DDIM;
    const uint32_t xW = (uint32_t)((rA & 7) << 4);
    int jr[4];
    uint32_t aDstOff[4];
    #pragma unroll
    for (int rd = 0; rd < 4; ++rd) {
        int p = rd * 16 + rA;
        jr[rd] = min(max(i - WWIN + k0 + p, 0), NN - 1);
        aDstOff[rd] = (uint32_t)(p * 128 + (((uint32_t)(c8 * 16)) ^ xW));
    }

    // =================== Stage 1: acc += (gi*gj) @ W1c (fp16) ==============
    // Prolog: B(kt=0) -> B[1]; A(kt=0) -> A[0]
    {
        const char* src = (const char*)g_W1hi;
        for (int x = tid; x < TILE_B_U4; x += NTHR)
            cp16(sb + SB + 19456 + x * 16, src + x * 16);
        CP_COMMIT();
        const uint4 gi16 = ((const uint4*)giBase)[c8];
        #pragma unroll
        for (int rd = 0; rd < 4; ++rd) {
            uint4 gj16 = ((const uint4*)(g_h + (size_t)jr[rd] * DDIM))[c8];
            *(uint4*)(smem + SA + aDstOff[rd]) = hmul_u4(gi16, gj16);
        }
        CP_WAIT0();
        __syncthreads();
    }

    for (int kt = 0; kt < 8; ++kt) {
        // issue next B tile (kt+1) -> B[kt&1]; at kt=7 this is the W2 t0 prefetch
        {
            const char* src = (kt < 7) ? (const char*)(g_W1hi + (kt + 1) * TILE_W_HALVES)
                                       : (const char*)g_W2hi;
            uint32_t dstB = sb + SB + (uint32_t)((kt & 1) * 19456);
            for (int x = tid; x < TILE_B_U4; x += NTHR)
                cp16(dstB + x * 16, src + x * 16);
            CP_COMMIT();
        }

        // MMA(kt): A[kt&1], B[(kt+1)&1]
        const uint32_t aB = sb + SA + (uint32_t)((kt & 1) * 8192);
        const uint32_t bB = sb + SB + (uint32_t)(((kt + 1) & 1) * 19456);
        #pragma unroll
        for (int ks = 0; ks < 4; ++ks) {
            const uint32_t ka = cbA + ks * 32;
            const uint32_t kb2 = cbB + ks * 32;
            uint32_t ah0[4], ah1[4];
            ldsm4(ah0, aB + aBase[0] + (ka ^ aXor[0]));
            ldsm4(ah1, aB + aBase[1] + (ka ^ aXor[1]));
            #pragma unroll
            for (int ntp = 0; ntp < 5; ++ntp) {
                uint32_t bf[4];
                ldsm4(bf, bB + bBase[ntp] + (kb2 ^ bXor[ntp]));
                mma16816(acc[0][2 * ntp],     ah0[0], ah0[1], ah0[2], ah0[3], bf[0], bf[1]);
                mma16816(acc[1][2 * ntp],     ah1[0], ah1[1], ah1[2], ah1[3], bf[0], bf[1]);
                if (ntp < 4 || !trim) {
                    mma16816(acc[0][2 * ntp + 1], ah0[0], ah0[1], ah0[2], ah0[3], bf[2], bf[3]);
                    mma16816(acc[1][2 * ntp + 1], ah1[0], ah1[1], ah1[2], ah1[3], bf[2], bf[3]);
                }
            }
        }

        // A-prep(kt+1) -> A[(kt+1)&1] (its readers synced at end of kt-1)
        if (kt < 7) {
            const uint4 gi16 = ((const uint4*)(giBase + (kt + 1) * 64))[c8];
            uint32_t aD = sb + SA + (uint32_t)(((kt + 1) & 1) * 8192);
            #pragma unroll
            for (int rd = 0; rd < 4; ++rd) {
                uint4 gj16 = ((const uint4*)(g_h + (size_t)jr[rd] * DDIM + (kt + 1) * 64))[c8];
                *(uint4*)(smem + (aD - sb) + aDstOff[rd]) = hmul_u4(gi16, gj16);
            }
        }
        CP_WAIT0();
        __syncthreads();        // ONE sync per k-tile
    }

    // ============ h1 = relu(acc) -> SMEM (fp16, swizzled tiles) ============
    // tiles: t0 -> SA, t1 -> SA+8192, t2 -> SB (B[0], dead after kt=7)
    {
        #pragma unroll
        for (int mi = 0; mi < 2; ++mi)
            #pragma unroll
            for (int h8 = 0; h8 < 2; ++h8) {
                int row = wm * 32 + mi * 16 + gq + h8 * 8;
                uint32_t xr = (uint32_t)((row & 7) << 4);
                #pragma unroll
                for (int nt = 0; nt < 10; ++nt) {
                    int col = wn * 80 + nt * 8 + 2 * t;
                    float v0 = fmaxf(acc[mi][nt][h8 * 2 + 0], 0.f);
                    float v1 = fmaxf(acc[mi][nt][h8 * 2 + 1], 0.f);
                    __half2 h = __float22half2_rn(make_float2(v0, v1));
                    int tile = col >> 6;
                    uint32_t tbase = (tile == 0) ? SA : ((tile == 1) ? (SA + 8192) : SB);
                    uint32_t off = tbase + (uint32_t)(row * 128)
                                 + (((uint32_t)((col & 63) * 2)) ^ xr);
                    *(uint32_t*)(smem + off) = *(uint32_t*)&h;
                }
            }
    }

    // ---- re-init acc with b2 for stage 2 ----
    #pragma unroll
    for (int nt = 0; nt < 10; ++nt)
        #pragma unroll
        for (int par = 0; par < 2; ++par) {
            int col = wn * 80 + nt * 8 + 2 * t + par;
            float bv = (col < HDIM) ? b2[col] : 0.f;
            #pragma unroll
            for (int mi = 0; mi < 2; ++mi)
                #pragma unroll
                for (int h8 = 0; h8 < 2; ++h8)
                    acc[mi][nt][h8 * 2 + par] = bv;
        }
    __syncthreads();          // h1 visible; W2 t0 already in SW2 (waited at kt=7)

    // ======== Stage 2: acc += relu(h1) @ W2 (fp16, K=160) ==================
    for (int kt2 = 0; kt2 < 3; ++kt2) {
        if (kt2 > 0) {
            const char* src = (const char*)(g_W2hi + kt2 * TILE_W_HALVES);
            for (int x = tid; x < TILE_B_U4; x += NTHR)
                cp16(sb + SW2 + x * 16, src + x * 16);
            CP_COMMIT();
            CP_WAIT0();
            __syncthreads();
        }
        const uint32_t aB2 = sb + ((kt2 == 0) ? SA : ((kt2 == 1) ? (SA + 8192) : SB));
        const int nks = (kt2 == 2) ? 2 : 4;
        for (int ks = 0; ks < nks; ++ks) {
            const uint32_t ka = cbA + ks * 32;
            const uint32_t kb2 = cbB + ks * 32;
            uint32_t af0[4], af1[4];
            ldsm4(af0, aB2 + aBase[0] + (ka ^ aXor[0]));
            ldsm4(af1, aB2 + aBase[1] + (ka ^ aXor[1]));
            #pragma unroll
            for (int ntp = 0; ntp < 5; ++ntp) {
                uint32_t bf[4];
                ldsm4(bf, sb + SW2 + bBase[ntp] + (kb2 ^ bXor[ntp]));
                mma16816(acc[0][2 * ntp],     af0[0], af0[1], af0[2], af0[3], bf[0], bf[1]);
                mma16816(acc[1][2 * ntp],     af1[0], af1[1], af1[2], af1[3], bf[0], bf[1]);
                if (ntp < 4 || !trim) {
                    mma16816(acc[0][2 * ntp + 1], af0[0], af0[1], af0[2], af0[3], bf[2], bf[3]);
                    mma16816(acc[1][2 * ntp + 1], af1[0], af1[1], af1[2], af1[3], bf[2], bf[3]);
                }
            }
        }
        __syncthreads();
    }

    // =================== Epilogue: relu(acc) @ W3, reduce ==================
    float rsum[2][2] = {{0.f, 0.f}, {0.f, 0.f}};
    #pragma unroll
    for (int nt = 0; nt < 10; ++nt)
        #pragma unroll
        for (int par = 0; par < 2; ++par) {
            int col = wn * 80 + nt * 8 + 2 * t + par;
            float w3 = (col < HDIM) ? W3[col] : 0.f;
            #pragma unroll
            for (int mi = 0; mi < 2; ++mi)
                #pragma unroll
                for (int h8 = 0; h8 < 2; ++h8)
                    rsum[mi][h8] += fmaxf(acc[mi][nt][h8 * 2 + par], 0.f) * w3;
        }
    #pragma unroll
    for (int mi = 0; mi < 2; ++mi)
        #pragma unroll
        for (int h8 = 0; h8 < 2; ++h8) {
            float v = rsum[mi][h8];
            v += __shfl_xor_sync(0xffffffffu, v, 1);
            v += __shfl_xor_sync(0xffffffffu, v, 2);
            rsum[mi][h8] = v;
        }

    float* sred = (float*)(smem + SRED);
    if (wn == 0 && t == 0) {
        #pragma unroll
        for (int mi = 0; mi < 2; ++mi)
            #pragma unroll
            for (int h8 = 0; h8 < 2; ++h8)
                sred[wm * 32 + mi * 16 + gq + h8 * 8] = rsum[mi][h8];
    }
    __syncthreads();
    if (wn == 1 && t == 0) {
        float smi = sm[i];
        float bb3 = b3[0];
        #pragma unroll
        for (int mi = 0; mi < 2; ++mi)
            #pragma unroll
            for (int h8 = 0; h8 < 2; ++h8) {
                int p = wm * 32 + mi * 16 + gq + h8 * 8;
                int k = k0 + p;
                int j = i - WWIN + k;
                float tot = rsum[mi][h8] + sred[p];
                if (k < WWIN) {
                    float val = 0.f;
                    if (j >= 0) val = tot + bb3 + smi + sm[j];
                    out[(size_t)i * OUTW + k] = val;
                } else if (k == WWIN) {
                    out[(size_t)i * OUTW + k] = 0.f;   // epsilon column
                }
            }
    }
}

// ---------------------------------------------------------------------------
extern "C" void kernel_launch(void* const* d_in, const int* in_sizes, int n_in,
                              void* d_out, int out_size)
{
    const float* g  = (const float*)d_in[0];
    const float* sm = (const float*)d_in[1];
    const float* W1 = (const float*)d_in[2];
    const float* b1 = (const float*)d_in[3];
    const float* W2 = (const float*)d_in[4];
    const float* b2 = (const float*)d_in[5];
    const float* W3 = (const float*)d_in[6];
    const float* b3 = (const float*)d_in[7];
    float* out = (float*)d_out;

    cudaFuncSetAttribute(pair_mma_kernel,
                         cudaFuncAttributeMaxDynamicSharedMemorySize, SMEM_TOTAL);

    precompute_all<<<267, 640>>>(g, W1, b1, W2);

    dim3 grid(4, NN);
    pair_mma_kernel<<<grid, NTHR, SMEM_TOTAL>>>(sm, b2, W3, b3, out);
}

// round 13
// speedup vs baseline: 1.0718x; 1.0365x over previous
#include <cuda_runtime.h>
#include <cuda_fp16.h>
#include <cstdint>

#define NN    1024
#define DDIM  512
#define HDIM  150
#define HP    160
#define WWIN  250
#define OUTW  251
#define NTHR  128
#define MT    64

// ---- dynamic SMEM byte offsets (main kernel) ----
#define SA    0
#define SB0   9216
#define SB1   31104
#define SB2   31104
#define SRED  52992
#define SMEM_TOTAL 53248

#define BROWS 152
#define TILE_B_BYTES (BROWS * 144)      // 21888
#define TILE_B_U4    (TILE_B_BYTES/16)  // 1368
#define TILE_W_HALVES (BROWS * 72)      // 10944

// gt-mma kernel tiles: 160 rows, pitch 144
#define GT_TILE_HALVES (HP * 72)        // 11520
#define GT_TILE_BYTES  (HP * 144)       // 23040
#define GT_TILE_U4     (GT_TILE_BYTES/16) // 1440
// gt-mma SMEM: A_HI 0..4608, A_LO 4608..9216, B[buf] at 9216+buf*46080 (HI,LO)
#define GT_A_HI 0
#define GT_A_LO 4608
#define GT_B    9216
#define GT_SMEM 101376

// ---------------------------------------------------------------------------
// Device scratch
// ---------------------------------------------------------------------------
__device__ float g_giT[NN * HP];      // g@W1a + b1, [i][h], zero pad h>=150
__device__ float g_gjT_T[HP * NN];    // (g@W1b)^T, [h][i], zero pad
__device__ __align__(16) __half g_h[NN * DDIM];   // fp16 copy of g
__device__ __align__(16) __half g_W1hi[8 * TILE_W_HALVES];
__device__ __align__(16) __half g_W2hi[3 * TILE_W_HALVES];
__device__ __align__(16) __half g_Wahi[8 * GT_TILE_HALVES];
__device__ __align__(16) __half g_Walo[8 * GT_TILE_HALVES];
__device__ __align__(16) __half g_Wbhi[8 * GT_TILE_HALVES];
__device__ __align__(16) __half g_Wblo[8 * GT_TILE_HALVES];

// ---------------------------------------------------------------------------
// Helpers
// ---------------------------------------------------------------------------
__device__ __forceinline__ uint32_t smem_u32(const void* p) {
    uint32_t a;
    asm("{ .reg .u64 t; cvta.to.shared.u64 t, %1; cvt.u32.u64 %0, t; }"
        : "=r"(a) : "l"(p));
    return a;
}

__device__ __forceinline__ void cp16(uint32_t s, const void* g) {
    asm volatile("{\n\t.reg .u64 gp;\n\tcvta.to.global.u64 gp, %1;\n\t"
                 "cp.async.cg.shared.global [%0], [gp], 16;\n\t}"
                 :: "r"(s), "l"(g) : "memory");
}
#define CP_COMMIT() asm volatile("cp.async.commit_group;" ::: "memory")
#define CP_WAIT0()  asm volatile("cp.async.wait_group 0;" ::: "memory")

__device__ __forceinline__ void ldsm4(uint32_t* r, uint32_t addr) {
    asm volatile("ldmatrix.sync.aligned.m8n8.x4.shared.b16 {%0,%1,%2,%3}, [%4];"
        : "=r"(r[0]), "=r"(r[1]), "=r"(r[2]), "=r"(r[3]) : "r"(addr));
}

__device__ __forceinline__ void mma16816(float* c,
    uint32_t a0, uint32_t a1, uint32_t a2, uint32_t a3,
    uint32_t b0, uint32_t b1)
{
    asm volatile(
        "mma.sync.aligned.m16n8k16.row.col.f32.f16.f16.f32 "
        "{%0,%1,%2,%3}, {%4,%5,%6,%7}, {%8,%9}, {%0,%1,%2,%3};"
        : "+f"(c[0]), "+f"(c[1]), "+f"(c[2]), "+f"(c[3])
        : "r"(a0), "r"(a1), "r"(a2), "r"(a3), "r"(b0), "r"(b1));
}

__device__ __forceinline__ uint4 hmul_u4(uint4 x, uint4 y) {
    __half2* xa = (__half2*)&x;
    __half2* ya = (__half2*)&y;
    uint4 r;
    __half2* ra = (__half2*)&r;
    ra[0] = __hmul2(xa[0], ya[0]);
    ra[1] = __hmul2(xa[1], ya[1]);
    ra[2] = __hmul2(xa[2], ya[2]);
    ra[3] = __hmul2(xa[3], ya[3]);
    return r;
}

// ---------------------------------------------------------------------------
// Kernel 1: weight tiles. 27 blocks x 256 thr.
//  bt 0..7  : W1c hi   -> g_W1hi (152 rows)
//  bt 8..10 : W2  hi   -> g_W2hi (152 rows)
//  bt 11..18: W1a hi+lo-> g_Wahi/g_Walo (160 rows)
//  bt 19..26: W1b hi+lo-> g_Wbhi/g_Wblo (160 rows)
// ---------------------------------------------------------------------------
__global__ void __launch_bounds__(256) precompute_w(
    const float* __restrict__ W1, const float* __restrict__ W2)
{
    const int bt = blockIdx.x;
    const int tid = threadIdx.x;
    const float* W1c = W1 + 2 * DDIM * HDIM;
    const float* W1b = W1 + DDIM * HDIM;

    if (bt < 8) {
        __half* dhi = g_W1hi + bt * TILE_W_HALVES;
        for (int idx = tid; idx < BROWS * 64; idx += 256) {
            int n = idx >> 6, k = idx & 63;
            int d = bt * 64 + k;
            float val = (n < HDIM) ? W1c[d * HDIM + n] : 0.f;
            dhi[n * 72 + k] = __float2half_rn(val);
        }
    } else if (bt < 11) {
        const int kt = bt - 8;
        __half* dhi = g_W2hi + kt * TILE_W_HALVES;
        for (int idx = tid; idx < BROWS * 64; idx += 256) {
            int n = idx >> 6, k = idx & 63;
            int kg = kt * 64 + k;
            float val = (kg < HDIM && n < HDIM) ? W2[kg * HDIM + n] : 0.f;
            dhi[n * 72 + k] = __float2half_rn(val);
        }
    } else {
        const bool isA = (bt < 19);
        const int kt = isA ? (bt - 11) : (bt - 19);
        const float* src = isA ? W1 : W1b;
        __half* dhi = (isA ? g_Wahi : g_Wbhi) + kt * GT_TILE_HALVES;
        __half* dlo = (isA ? g_Walo : g_Wblo) + kt * GT_TILE_HALVES;
        for (int idx = tid; idx < HP * 64; idx += 256) {
            int n = idx >> 6, k = idx & 63;
            int d = kt * 64 + k;
            float val = (n < HDIM) ? src[d * HDIM + n] : 0.f;
            __half h = __float2half_rn(val);
            __half l = __float2half_rn(val - __half2float(h));
            dhi[n * 72 + k] = h;
            dlo[n * 72 + k] = l;
        }
    }
}

// ---------------------------------------------------------------------------
// Kernel 2: gt GEMM via fp16-split MMA (3 products). grid (2, 32), 128 thr.
//  gw=0: giT[i][h] = g @ W1a + b1 (and writes g_h = fp16(g))
//  gw=1: gjT_T[h][i] = (g @ W1b)^T
// CTA = 32 rows of g x N=160. 4 warps: wm=wid&1 (16 rows), wn=wid>>1 (80 cols).
// ---------------------------------------------------------------------------
__global__ void __launch_bounds__(128) precompute_gt_mma(
    const float* __restrict__ g, const float* __restrict__ b1)
{
    extern __shared__ char smem[];
    const uint32_t sb = smem_u32(smem);
    const int tid = threadIdx.x;
    const int gw = blockIdx.x;
    const int i0 = blockIdx.y * 32;

    const int wid = tid >> 5, lid = tid & 31;
    const int wm = wid & 1, wn = wid >> 1;
    const int gq = lid >> 2, t = lid & 3;
    const int mq = lid >> 3, rr = lid & 7;

    const __half* Whi = gw ? g_Wbhi : g_Wahi;
    const __half* Wlo = gw ? g_Wblo : g_Walo;

    float acc[10][4];
    #pragma unroll
    for (int nt = 0; nt < 10; ++nt)
        #pragma unroll
        for (int q = 0; q < 4; ++q) acc[nt][q] = 0.f;

    const uint32_t aOff = (uint32_t)((wm * 16 + (mq & 1) * 8 + rr) * 144 + (mq >> 1) * 16);
    uint32_t bOff[5];
    #pragma unroll
    for (int ntp = 0; ntp < 5; ++ntp) {
        int rowb = wn * 80 + (ntp * 2 + (mq >> 1)) * 8 + rr;
        bOff[ntp] = (uint32_t)(rowb * 144 + (mq & 1) * 16);
    }

    // A-prep mapping: pA = tid>>2 (row 0..31), sA = tid&3 (16-float chunk)
    const int pA = tid >> 2;
    const int sA = tid & 3;
    const float4* gRow = (const float4*)(g + (size_t)(i0 + pA) * DDIM) + sA * 4;

    auto a_prep = [&](int kt) {
        float4 v[4];
        #pragma unroll
        for (int q = 0; q < 4; ++q) v[q] = gRow[kt * 16 + q];
        uint32_t hi[8], lo[8];
        #pragma unroll
        for (int q = 0; q < 4; ++q) {
            const float* f = (const float*)&v[q];
            __half2 h0 = __float22half2_rn(make_float2(f[0], f[1]));
            __half2 h1 = __float22half2_rn(make_float2(f[2], f[3]));
            float r0 = f[0] - __low2float(h0), r1 = f[1] - __high2float(h0);
            float r2 = f[2] - __low2float(h1), r3 = f[3] - __high2float(h1);
            __half2 l0 = __float22half2_rn(make_float2(r0, r1));
            __half2 l1 = __float22half2_rn(make_float2(r2, r3));
            hi[2 * q] = *(uint32_t*)&h0; hi[2 * q + 1] = *(uint32_t*)&h1;
            lo[2 * q] = *(uint32_t*)&l0; lo[2 * q + 1] = *(uint32_t*)&l1;
        }
        char* dh = smem + GT_A_HI + pA * 144 + sA * 32;
        char* dl = smem + GT_A_LO + pA * 144 + sA * 32;
        *(uint4*)(dh)      = make_uint4(hi[0], hi[1], hi[2], hi[3]);
        *(uint4*)(dh + 16) = make_uint4(hi[4], hi[5], hi[6], hi[7]);
        *(uint4*)(dl)      = make_uint4(lo[0], lo[1], lo[2], lo[3]);
        *(uint4*)(dl + 16) = make_uint4(lo[4], lo[5], lo[6], lo[7]);
        if (gw == 0) {   // g_h = fp16(g), written once (gw=0 grid covers all rows)
            uint4* gh = (uint4*)(g_h + (size_t)(i0 + pA) * DDIM + kt * 64 + sA * 16);
            gh[0] = make_uint4(hi[0], hi[1], hi[2], hi[3]);
            gh[1] = make_uint4(hi[4], hi[5], hi[6], hi[7]);
        }
    };

    // Prolog: B(0) -> buf0; A(0)
    {
        const char* shi = (const char*)Whi;
        const char* slo = (const char*)Wlo;
        for (int x = tid; x < GT_TILE_U4; x += 128) {
            cp16(sb + GT_B + x * 16, shi + x * 16);
            cp16(sb + GT_B + GT_TILE_BYTES + x * 16, slo + x * 16);
        }
        CP_COMMIT();
        a_prep(0);
        CP_WAIT0();
        __syncthreads();
    }

    for (int kt = 0; kt < 8; ++kt) {
        if (kt < 7) {
            const char* shi = (const char*)(Whi + (kt + 1) * GT_TILE_HALVES);
            const char* slo = (const char*)(Wlo + (kt + 1) * GT_TILE_HALVES);
            uint32_t dstB = sb + GT_B + (uint32_t)(((kt + 1) & 1) * 46080);
            for (int x = tid; x < GT_TILE_U4; x += 128) {
                cp16(dstB + x * 16, shi + x * 16);
                cp16(dstB + GT_TILE_BYTES + x * 16, slo + x * 16);
            }
            CP_COMMIT();
        }

        const uint32_t bB = sb + GT_B + (uint32_t)((kt & 1) * 46080);
        #pragma unroll
        for (int ks = 0; ks < 4; ++ks) {
            uint32_t ahi[4], alo[4];
            ldsm4(ahi, sb + GT_A_HI + aOff + ks * 32);
            ldsm4(alo, sb + GT_A_LO + aOff + ks * 32);
            #pragma unroll
            for (int ntp = 0; ntp < 5; ++ntp) {
                uint32_t bh[4], bl[4];
                ldsm4(bh, bB + bOff[ntp] + ks * 32);
                mma16816(acc[2 * ntp],     ahi[0], ahi[1], ahi[2], ahi[3], bh[0], bh[1]);
                mma16816(acc[2 * ntp + 1], ahi[0], ahi[1], ahi[2], ahi[3], bh[2], bh[3]);
                mma16816(acc[2 * ntp],     alo[0], alo[1], alo[2], alo[3], bh[0], bh[1]);
                mma16816(acc[2 * ntp + 1], alo[0], alo[1], alo[2], alo[3], bh[2], bh[3]);
                ldsm4(bl, bB + GT_TILE_BYTES + bOff[ntp] + ks * 32);
                mma16816(acc[2 * ntp],     ahi[0], ahi[1], ahi[2], ahi[3], bl[0], bl[1]);
                mma16816(acc[2 * ntp + 1], ahi[0], ahi[1], ahi[2], ahi[3], bl[2], bl[3]);
            }
        }
        __syncthreads();
        if (kt < 7) a_prep(kt + 1);
        CP_WAIT0();
        __syncthreads();
    }

    // Epilogue: scatter accumulators
    const int r0 = i0 + wm * 16 + gq;
    const int r1 = r0 + 8;
    #pragma unroll
    for (int nt = 0; nt < 10; ++nt)
        #pragma unroll
        for (int par = 0; par < 2; ++par) {
            int col = wn * 80 + nt * 8 + 2 * t + par;
            float v0 = acc[nt][par], v1 = acc[nt][2 + par];
            if (gw == 0) {
                float bb = (col < HDIM) ? b1[col] : 0.f;
                g_giT[r0 * HP + col] = v0 + bb;
                g_giT[r1 * HP + col] = v1 + bb;
            } else {
                g_gjT_T[col * NN + r0] = v0;
                g_gjT_T[col * NN + r1] = v1;
            }
        }
}

// ---------------------------------------------------------------------------
// Main kernel (R10 verbatim). CTA = (i, 64 pairs). grid (4, 1024), 128 thr,
// 4 CTAs/SM. A single-buffered, B double-buffered, N=152, coalesced A-prep.
// ---------------------------------------------------------------------------
__global__ void __launch_bounds__(NTHR, 4) pair_mma_kernel(
    const float* __restrict__ sm, const float* __restrict__ b2,
    const float* __restrict__ W3, const float* __restrict__ b3,
    float* __restrict__ out)
{
    extern __shared__ char smem[];
    const uint32_t sb = smem_u32(smem);
    const int tid = threadIdx.x;
    const int i  = blockIdx.y;
    const int k0 = blockIdx.x * MT;

    if (i - WWIN + k0 + (MT - 1) < 0) {
        if (tid < MT) out[(size_t)i * OUTW + k0 + tid] = 0.f;
        return;
    }

    const int wid = tid >> 5, lid = tid & 31;
    const int wm = wid & 1, wn = wid >> 1;
    const int gq = lid >> 2, t = lid & 3;
    const bool trim = (wn == 1);

    int jrow[2][2];
    #pragma unroll
    for (int mi = 0; mi < 2; ++mi)
        #pragma unroll
        for (int h8 = 0; h8 < 2; ++h8) {
            int p = wm * 32 + mi * 16 + gq + h8 * 8;
            int j = i - WWIN + k0 + p;
            jrow[mi][h8] = min(max(j, 0), NN - 1);
        }

    float acc[2][10][4];
    {
        const float* giR = g_giT + i * HP;
        #pragma unroll
        for (int nt = 0; nt < 10; ++nt)
            #pragma unroll
            for (int par = 0; par < 2; ++par) {
                int col = wn * 80 + nt * 8 + 2 * t + par;
                float gic = giR[col];
                const float* gjc = g_gjT_T + col * NN;
                #pragma unroll
                for (int mi = 0; mi < 2; ++mi)
                    #pragma unroll
                    for (int h8 = 0; h8 < 2; ++h8)
                        acc[mi][nt][h8 * 2 + par] = gic + gjc[jrow[mi][h8]];
            }
    }

    const int mq = lid >> 3, rr = lid & 7;
    uint32_t aOff[2], bOff[5];
    #pragma unroll
    for (int mi = 0; mi < 2; ++mi)
        aOff[mi] = (uint32_t)((wm * 32 + mi * 16 + (mq & 1) * 8 + rr) * 144 + (mq >> 1) * 16);
    #pragma unroll
    for (int ntp = 0; ntp < 5; ++ntp) {
        int rowb = wn * 80 + (ntp * 2 + (mq >> 1)) * 8 + rr;
        if (rowb > 151) rowb = 151;
        bOff[ntp] = (uint32_t)(rowb * 144 + (mq & 1) * 16);
    }

    const int c8 = tid & 7;
    const int rA = tid >> 3;
    const __half* giBase = g_h + (size_t)i * DDIM;
    int jr[4];
    #pragma unroll
    for (int rd = 0; rd < 4; ++rd) {
        int p = rd * 16 + rA;
        jr[rd] = min(max(i - WWIN + k0 + p, 0), NN - 1);
    }

    {
        const char* src = (const char*)g_W1hi;
        for (int x = tid; x < TILE_B_U4; x += NTHR)
            cp16(sb + SB1 + x * 16, src + x * 16);
        CP_COMMIT();
        const uint4 gi16 = ((const uint4*)giBase)[c8];
        #pragma unroll
        for (int rd = 0; rd < 4; ++rd) {
            uint4 gj16 = ((const uint4*)(g_h + (size_t)jr[rd] * DDIM))[c8];
            *(uint4*)(smem + SA + (rd * 16 + rA) * 144 + c8 * 16) = hmul_u4(gi16, gj16);
        }
        CP_WAIT0();
        __syncthreads();
    }

    for (int kt = 0; kt < 8; ++kt) {
        if (kt < 7) {
            const char* src = (const char*)(g_W1hi + (kt + 1) * TILE_W_HALVES);
            uint32_t dstB = sb + (((kt + 1) & 1) ? SB0 : SB1);
            for (int x = tid; x < TILE_B_U4; x += NTHR)
                cp16(dstB + x * 16, src + x * 16);
            CP_COMMIT();
        } else {
            const char* src = (const char*)g_W2hi;
            for (int x = tid; x < TILE_B_U4; x += NTHR)
                cp16(sb + SB2 + x * 16, src + x * 16);
            CP_COMMIT();
        }

        const uint32_t bB = sb + ((kt & 1) ? SB0 : SB1);
        #pragma unroll
        for (int ks = 0; ks < 4; ++ks) {
            uint32_t ah0[4], ah1[4];
            ldsm4(ah0, sb + SA + aOff[0] + ks * 32);
            ldsm4(ah1, sb + SA + aOff[1] + ks * 32);
            #pragma unroll
            for (int ntp = 0; ntp < 5; ++ntp) {
                uint32_t bf[4];
                ldsm4(bf, bB + bOff[ntp] + ks * 32);
                mma16816(acc[0][2 * ntp],     ah0[0], ah0[1], ah0[2], ah0[3], bf[0], bf[1]);
                mma16816(acc[1][2 * ntp],     ah1[0], ah1[1], ah1[2], ah1[3], bf[0], bf[1]);
                if (ntp < 4 || !trim) {
                    mma16816(acc[0][2 * ntp + 1], ah0[0], ah0[1], ah0[2], ah0[3], bf[2], bf[3]);
                    mma16816(acc[1][2 * ntp + 1], ah1[0], ah1[1], ah1[2], ah1[3], bf[2], bf[3]);
                }
            }
        }
        __syncthreads();

        if (kt < 7) {
            const uint4 gi16 = ((const uint4*)(giBase + (kt + 1) * 64))[c8];
            #pragma unroll
            for (int rd = 0; rd < 4; ++rd) {
                uint4 gj16 = ((const uint4*)(g_h + (size_t)jr[rd] * DDIM + (kt + 1) * 64))[c8];
                *(uint4*)(smem + SA + (rd * 16 + rA) * 144 + c8 * 16) = hmul_u4(gi16, gj16);
            }
        }
        CP_WAIT0();
        __syncthreads();
    }

    {
        #pragma unroll
        for (int mi = 0; mi < 2; ++mi)
            #pragma unroll
            for (int h8 = 0; h8 < 2; ++h8) {
                int row = wm * 32 + mi * 16 + gq + h8 * 8;
                #pragma unroll
                for (int nt = 0; nt < 10; ++nt) {
                    int col = wn * 80 + nt * 8 + 2 * t;
                    float v0 = fmaxf(acc[mi][nt][h8 * 2 + 0], 0.f);
                    float v1 = fmaxf(acc[mi][nt][h8 * 2 + 1], 0.f);
                    __half2 h = __float22half2_rn(make_float2(v0, v1));
                    int tile = col >> 6;
                    uint32_t off = (uint32_t)(tile * 9216 + row * 144 + (col & 63) * 2);
                    *(uint32_t*)(smem + off) = *(uint32_t*)&h;
                }
            }
    }

    #pragma unroll
    for (int nt = 0; nt < 10; ++nt)
        #pragma unroll
        for (int par = 0; par < 2; ++par) {
            int col = wn * 80 + nt * 8 + 2 * t + par;
            float bv = (col < HDIM) ? b2[col] : 0.f;
            #pragma unroll
            for (int mi = 0; mi < 2; ++mi)
                #pragma unroll
                for (int h8 = 0; h8 < 2; ++h8)
                    acc[mi][nt][h8 * 2 + par] = bv;
        }
    __syncthreads();

    for (int kt2 = 0; kt2 < 3; ++kt2) {
        if (kt2 > 0) {
            const char* src = (const char*)(g_W2hi + kt2 * TILE_W_HALVES);
            for (int x = tid; x < TILE_B_U4; x += NTHR)
                cp16(sb + SB2 + x * 16, src + x * 16);
            CP_COMMIT();
            CP_WAIT0();
            __syncthreads();
        }
        const uint32_t aB2 = sb + kt2 * 9216;
        const int nks = (kt2 == 2) ? 2 : 4;
        for (int ks = 0; ks < nks; ++ks) {
            uint32_t af0[4], af1[4];
            ldsm4(af0, aB2 + aOff[0] + ks * 32);
            ldsm4(af1, aB2 + aOff[1] + ks * 32);
            #pragma unroll
            for (int ntp = 0; ntp < 5; ++ntp) {
                uint32_t bf[4];
                ldsm4(bf, sb + SB2 + bOff[ntp] + ks * 32);
                mma16816(acc[0][2 * ntp],     af0[0], af0[1], af0[2], af0[3], bf[0], bf[1]);
                mma16816(acc[1][2 * ntp],     af1[0], af1[1], af1[2], af1[3], bf[0], bf[1]);
                if (ntp < 4 || !trim) {
                    mma16816(acc[0][2 * ntp + 1], af0[0], af0[1], af0[2], af0[3], bf[2], bf[3]);
                    mma16816(acc[1][2 * ntp + 1], af1[0], af1[1], af1[2], af1[3], bf[2], bf[3]);
                }
            }
        }
        __syncthreads();
    }

    float rsum[2][2] = {{0.f, 0.f}, {0.f, 0.f}};
    #pragma unroll
    for (int nt = 0; nt < 10; ++nt)
        #pragma unroll
        for (int par = 0; par < 2; ++par) {
            int col = wn * 80 + nt * 8 + 2 * t + par;
            float w3 = (col < HDIM) ? W3[col] : 0.f;
            #pragma unroll
            for (int mi = 0; mi < 2; ++mi)
                #pragma unroll
                for (int h8 = 0; h8 < 2; ++h8)
                    rsum[mi][h8] += fmaxf(acc[mi][nt][h8 * 2 + par], 0.f) * w3;
        }
    #pragma unroll
    for (int mi = 0; mi < 2; ++mi)
        #pragma unroll
        for (int h8 = 0; h8 < 2; ++h8) {
            float v = rsum[mi][h8];
            v += __shfl_xor_sync(0xffffffffu, v, 1);
            v += __shfl_xor_sync(0xffffffffu, v, 2);
            rsum[mi][h8] = v;
        }

    float* sred = (float*)(smem + SRED);
    if (wn == 0 && t == 0) {
        #pragma unroll
        for (int mi = 0; mi < 2; ++mi)
            #pragma unroll
            for (int h8 = 0; h8 < 2; ++h8)
                sred[wm * 32 + mi * 16 + gq + h8 * 8] = rsum[mi][h8];
    }
    __syncthreads();
    if (wn == 1 && t == 0) {
        float smi = sm[i];
        float bb3 = b3[0];
        #pragma unroll
        for (int mi = 0; mi < 2; ++mi)
            #pragma unroll
            for (int h8 = 0; h8 < 2; ++h8) {
                int p = wm * 32 + mi * 16 + gq + h8 * 8;
                int k = k0 + p;
                int j = i - WWIN + k;
                float tot = rsum[mi][h8] + sred[p];
                if (k < WWIN) {
                    float val = 0.f;
                    if (j >= 0) val = tot + bb3 + smi + sm[j];
                    out[(size_t)i * OUTW + k] = val;
                } else if (k == WWIN) {
                    out[(size_t)i * OUTW + k] = 0.f;   // epsilon column
                }
            }
    }
}

// ---------------------------------------------------------------------------
extern "C" void kernel_launch(void* const* d_in, const int* in_sizes, int n_in,
                              void* d_out, int out_size)
{
    const float* g  = (const float*)d_in[0];
    const float* sm = (const float*)d_in[1];
    const float* W1 = (const float*)d_in[2];
    const float* b1 = (const float*)d_in[3];
    const float* W2 = (const float*)d_in[4];
    const float* b2 = (const float*)d_in[5];
    const float* W3 = (const float*)d_in[6];
    const float* b3 = (const float*)d_in[7];
    float* out = (float*)d_out;

    cudaFuncSetAttribute(pair_mma_kernel,
                         cudaFuncAttributeMaxDynamicSharedMemorySize, SMEM_TOTAL);
    cudaFuncSetAttribute(precompute_gt_mma,
                         cudaFuncAttributeMaxDynamicSharedMemorySize, GT_SMEM);

    precompute_w<<<27, 256>>>(W1, W2);
    dim3 ggrid(2, 32);
    precompute_gt_mma<<<ggrid, 128, GT_SMEM>>>(g, b1);

    dim3 grid(4, NN);
    pair_mma_kernel<<<grid, NTHR, SMEM_TOTAL>>>(sm, b2, W3, b3, out);
}

// round 14
// speedup vs baseline: 1.0873x; 1.0145x over previous
#include <cuda_runtime.h>
#include <cuda_fp16.h>
#include <cstdint>

#define NN    1024
#define DDIM  512
#define HDIM  150
#define HP    160
#define WWIN  250
#define OUTW  251
#define NTHR  128
#define MT    64

// ---- dynamic SMEM byte offsets (main kernel) ----
#define SA    0
#define SB0   9216
#define SB1   31104
#define SB2   31104
#define SRED  52992
#define SMEM_TOTAL 53248

#define BROWS 152
#define TILE_B_BYTES (BROWS * 144)      // 21888
#define TILE_B_U4    (TILE_B_BYTES/16)  // 1368
#define TILE_W_HALVES (BROWS * 72)      // 10944

// gt-mma kernel tiles: 160 rows, pitch 144
#define GT_TILE_HALVES (HP * 72)        // 11520
#define GT_TILE_BYTES  (HP * 144)       // 23040
#define GT_TILE_U4     (GT_TILE_BYTES/16) // 1440
// gt-mma SMEM: A_HI 0..4608, A_LO 4608..9216, B[buf] at 9216+buf*46080 (HI,LO)
#define GT_A_HI 0
#define GT_A_LO 4608
#define GT_B    9216
#define GT_SMEM 101376

// ---------------------------------------------------------------------------
// Device scratch
// ---------------------------------------------------------------------------
__device__ float g_giT[NN * HP];      // g@W1a + b1, [i][h], zero pad h>=150
__device__ float g_gjT_T[HP * NN];    // (g@W1b)^T, [h][i], zero pad
__device__ __align__(16) __half g_h[NN * DDIM];   // fp16 copy of g
__device__ __align__(16) __half g_W1hi[8 * TILE_W_HALVES];
__device__ __align__(16) __half g_W2hi[3 * TILE_W_HALVES];
__device__ __align__(16) __half g_Wahi[8 * GT_TILE_HALVES];
__device__ __align__(16) __half g_Walo[8 * GT_TILE_HALVES];
__device__ __align__(16) __half g_Wbhi[8 * GT_TILE_HALVES];
__device__ __align__(16) __half g_Wblo[8 * GT_TILE_HALVES];

// ---------------------------------------------------------------------------
// Helpers
// ---------------------------------------------------------------------------
__device__ __forceinline__ uint32_t smem_u32(const void* p) {
    uint32_t a;
    asm("{ .reg .u64 t; cvta.to.shared.u64 t, %1; cvt.u32.u64 %0, t; }"
        : "=r"(a) : "l"(p));
    return a;
}

__device__ __forceinline__ void cp16(uint32_t s, const void* g) {
    asm volatile("{\n\t.reg .u64 gp;\n\tcvta.to.global.u64 gp, %1;\n\t"
                 "cp.async.cg.shared.global [%0], [gp], 16;\n\t}"
                 :: "r"(s), "l"(g) : "memory");
}
#define CP_COMMIT() asm volatile("cp.async.commit_group;" ::: "memory")
#define CP_WAIT0()  asm volatile("cp.async.wait_group 0;" ::: "memory")

__device__ __forceinline__ void ldsm4(uint32_t* r, uint32_t addr) {
    asm volatile("ldmatrix.sync.aligned.m8n8.x4.shared.b16 {%0,%1,%2,%3}, [%4];"
        : "=r"(r[0]), "=r"(r[1]), "=r"(r[2]), "=r"(r[3]) : "r"(addr));
}

__device__ __forceinline__ void mma16816(float* c,
    uint32_t a0, uint32_t a1, uint32_t a2, uint32_t a3,
    uint32_t b0, uint32_t b1)
{
    asm volatile(
        "mma.sync.aligned.m16n8k16.row.col.f32.f16.f16.f32 "
        "{%0,%1,%2,%3}, {%4,%5,%6,%7}, {%8,%9}, {%0,%1,%2,%3};"
        : "+f"(c[0]), "+f"(c[1]), "+f"(c[2]), "+f"(c[3])
        : "r"(a0), "r"(a1), "r"(a2), "r"(a3), "r"(b0), "r"(b1));
}

__device__ __forceinline__ uint4 hmul_u4(uint4 x, uint4 y) {
    __half2* xa = (__half2*)&x;
    __half2* ya = (__half2*)&y;
    uint4 r;
    __half2* ra = (__half2*)&r;
    ra[0] = __hmul2(xa[0], ya[0]);
    ra[1] = __hmul2(xa[1], ya[1]);
    ra[2] = __hmul2(xa[2], ya[2]);
    ra[3] = __hmul2(xa[3], ya[3]);
    return r;
}

// ---------------------------------------------------------------------------
// Kernel 1: weight tiles. grid (27, 8) x 256 thr — each tile split 8 ways.
//  bt 0..7  : W1c hi   -> g_W1hi (152 rows)
//  bt 8..10 : W2  hi   -> g_W2hi (152 rows)
//  bt 11..18: W1a hi+lo-> g_Wahi/g_Walo (160 rows)
//  bt 19..26: W1b hi+lo-> g_Wbhi/g_Wblo (160 rows)
// ---------------------------------------------------------------------------
__global__ void __launch_bounds__(256) precompute_w(
    const float* __restrict__ W1, const float* __restrict__ W2)
{
    const int bt = blockIdx.x;
    const int sl = blockIdx.y;              // slice 0..7
    const int tid = threadIdx.x;
    const int start = sl * 256 + tid;
    const int step  = 8 * 256;
    const float* W1c = W1 + 2 * DDIM * HDIM;
    const float* W1b = W1 + DDIM * HDIM;

    if (bt < 8) {
        __half* dhi = g_W1hi + bt * TILE_W_HALVES;
        for (int idx = start; idx < BROWS * 64; idx += step) {
            int n = idx >> 6, k = idx & 63;
            int d = bt * 64 + k;
            float val = (n < HDIM) ? W1c[d * HDIM + n] : 0.f;
            dhi[n * 72 + k] = __float2half_rn(val);
        }
    } else if (bt < 11) {
        const int kt = bt - 8;
        __half* dhi = g_W2hi + kt * TILE_W_HALVES;
        for (int idx = start; idx < BROWS * 64; idx += step) {
            int n = idx >> 6, k = idx & 63;
            int kg = kt * 64 + k;
            float val = (kg < HDIM && n < HDIM) ? W2[kg * HDIM + n] : 0.f;
            dhi[n * 72 + k] = __float2half_rn(val);
        }
    } else {
        const bool isA = (bt < 19);
        const int kt = isA ? (bt - 11) : (bt - 19);
        const float* src = isA ? W1 : W1b;
        __half* dhi = (isA ? g_Wahi : g_Wbhi) + kt * GT_TILE_HALVES;
        __half* dlo = (isA ? g_Walo : g_Wblo) + kt * GT_TILE_HALVES;
        for (int idx = start; idx < HP * 64; idx += step) {
            int n = idx >> 6, k = idx & 63;
            int d = kt * 64 + k;
            float val = (n < HDIM) ? src[d * HDIM + n] : 0.f;
            __half h = __float2half_rn(val);
            __half l = __float2half_rn(val - __half2float(h));
            dhi[n * 72 + k] = h;
            dlo[n * 72 + k] = l;
        }
    }
}

// ---------------------------------------------------------------------------
// Kernel 2: gt GEMM via fp16-split MMA (3 products). grid (2, 32), 128 thr.
//  gw=0: giT[i][h] = g @ W1a + b1 (and writes g_h = fp16(g))
//  gw=1: gjT_T[h][i] = (g @ W1b)^T
// CTA = 32 rows of g x N=160. 4 warps: wm=wid&1 (16 rows), wn=wid>>1 (80 cols).
// ---------------------------------------------------------------------------
__global__ void __launch_bounds__(128) precompute_gt_mma(
    const float* __restrict__ g, const float* __restrict__ b1)
{
    extern __shared__ char smem[];
    const uint32_t sb = smem_u32(smem);
    const int tid = threadIdx.x;
    const int gw = blockIdx.x;
    const int i0 = blockIdx.y * 32;

    const int wid = tid >> 5, lid = tid & 31;
    const int wm = wid & 1, wn = wid >> 1;
    const int gq = lid >> 2, t = lid & 3;
    const int mq = lid >> 3, rr = lid & 7;

    const __half* Whi = gw ? g_Wbhi : g_Wahi;
    const __half* Wlo = gw ? g_Wblo : g_Walo;

    float acc[10][4];
    #pragma unroll
    for (int nt = 0; nt < 10; ++nt)
        #pragma unroll
        for (int q = 0; q < 4; ++q) acc[nt][q] = 0.f;

    const uint32_t aOff = (uint32_t)((wm * 16 + (mq & 1) * 8 + rr) * 144 + (mq >> 1) * 16);
    uint32_t bOff[5];
    #pragma unroll
    for (int ntp = 0; ntp < 5; ++ntp) {
        int rowb = wn * 80 + (ntp * 2 + (mq >> 1)) * 8 + rr;
        bOff[ntp] = (uint32_t)(rowb * 144 + (mq & 1) * 16);
    }

    // A-prep mapping: pA = tid>>2 (row 0..31), sA = tid&3 (16-float chunk)
    const int pA = tid >> 2;
    const int sA = tid & 3;
    const float4* gRow = (const float4*)(g + (size_t)(i0 + pA) * DDIM) + sA * 4;

    auto a_prep = [&](int kt) {
        float4 v[4];
        #pragma unroll
        for (int q = 0; q < 4; ++q) v[q] = gRow[kt * 16 + q];
        uint32_t hi[8], lo[8];
        #pragma unroll
        for (int q = 0; q < 4; ++q) {
            const float* f = (const float*)&v[q];
            __half2 h0 = __float22half2_rn(make_float2(f[0], f[1]));
            __half2 h1 = __float22half2_rn(make_float2(f[2], f[3]));
            float r0 = f[0] - __low2float(h0), r1 = f[1] - __high2float(h0);
            float r2 = f[2] - __low2float(h1), r3 = f[3] - __high2float(h1);
            __half2 l0 = __float22half2_rn(make_float2(r0, r1));
            __half2 l1 = __float22half2_rn(make_float2(r2, r3));
            hi[2 * q] = *(uint32_t*)&h0; hi[2 * q + 1] = *(uint32_t*)&h1;
            lo[2 * q] = *(uint32_t*)&l0; lo[2 * q + 1] = *(uint32_t*)&l1;
        }
        char* dh = smem + GT_A_HI + pA * 144 + sA * 32;
        char* dl = smem + GT_A_LO + pA * 144 + sA * 32;
        *(uint4*)(dh)      = make_uint4(hi[0], hi[1], hi[2], hi[3]);
        *(uint4*)(dh + 16) = make_uint4(hi[4], hi[5], hi[6], hi[7]);
        *(uint4*)(dl)      = make_uint4(lo[0], lo[1], lo[2], lo[3]);
        *(uint4*)(dl + 16) = make_uint4(lo[4], lo[5], lo[6], lo[7]);
        if (gw == 0) {   // g_h = fp16(g), written once (gw=0 grid covers all rows)
            uint4* gh = (uint4*)(g_h + (size_t)(i0 + pA) * DDIM + kt * 64 + sA * 16);
            gh[0] = make_uint4(hi[0], hi[1], hi[2], hi[3]);
            gh[1] = make_uint4(hi[4], hi[5], hi[6], hi[7]);
        }
    };

    // Prolog: B(0) -> buf0; A(0)
    {
        const char* shi = (const char*)Whi;
        const char* slo = (const char*)Wlo;
        for (int x = tid; x < GT_TILE_U4; x += 128) {
            cp16(sb + GT_B + x * 16, shi + x * 16);
            cp16(sb + GT_B + GT_TILE_BYTES + x * 16, slo + x * 16);
        }
        CP_COMMIT();
        a_prep(0);
        CP_WAIT0();
        __syncthreads();
    }

    for (int kt = 0; kt < 8; ++kt) {
        if (kt < 7) {
            const char* shi = (const char*)(Whi + (kt + 1) * GT_TILE_HALVES);
            const char* slo = (const char*)(Wlo + (kt + 1) * GT_TILE_HALVES);
            uint32_t dstB = sb + GT_B + (uint32_t)(((kt + 1) & 1) * 46080);
            for (int x = tid; x < GT_TILE_U4; x += 128) {
                cp16(dstB + x * 16, shi + x * 16);
                cp16(dstB + GT_TILE_BYTES + x * 16, slo + x * 16);
            }
            CP_COMMIT();
        }

        const uint32_t bB = sb + GT_B + (uint32_t)((kt & 1) * 46080);
        #pragma unroll
        for (int ks = 0; ks < 4; ++ks) {
            uint32_t ahi[4], alo[4];
            ldsm4(ahi, sb + GT_A_HI + aOff + ks * 32);
            ldsm4(alo, sb + GT_A_LO + aOff + ks * 32);
            #pragma unroll
            for (int ntp = 0; ntp < 5; ++ntp) {
                uint32_t bh[4], bl[4];
                ldsm4(bh, bB + bOff[ntp] + ks * 32);
                mma16816(acc[2 * ntp],     ahi[0], ahi[1], ahi[2], ahi[3], bh[0], bh[1]);
                mma16816(acc[2 * ntp + 1], ahi[0], ahi[1], ahi[2], ahi[3], bh[2], bh[3]);
                mma16816(acc[2 * ntp],     alo[0], alo[1], alo[2], alo[3], bh[0], bh[1]);
                mma16816(acc[2 * ntp + 1], alo[0], alo[1], alo[2], alo[3], bh[2], bh[3]);
                ldsm4(bl, bB + GT_TILE_BYTES + bOff[ntp] + ks * 32);
                mma16816(acc[2 * ntp],     ahi[0], ahi[1], ahi[2], ahi[3], bl[0], bl[1]);
                mma16816(acc[2 * ntp + 1], ahi[0], ahi[1], ahi[2], ahi[3], bl[2], bl[3]);
            }
        }
        __syncthreads();
        if (kt < 7) a_prep(kt + 1);
        CP_WAIT0();
        __syncthreads();
    }

    // Epilogue: scatter accumulators
    const int r0 = i0 + wm * 16 + gq;
    const int r1 = r0 + 8;
    #pragma unroll
    for (int nt = 0; nt < 10; ++nt)
        #pragma unroll
        for (int par = 0; par < 2; ++par) {
            int col = wn * 80 + nt * 8 + 2 * t + par;
            float v0 = acc[nt][par], v1 = acc[nt][2 + par];
            if (gw == 0) {
                float bb = (col < HDIM) ? b1[col] : 0.f;
                g_giT[r0 * HP + col] = v0 + bb;
                g_giT[r1 * HP + col] = v1 + bb;
            } else {
                g_gjT_T[col * NN + r0] = v0;
                g_gjT_T[col * NN + r1] = v1;
            }
        }
}

// ---------------------------------------------------------------------------
// Main kernel (R10 verbatim). CTA = (i, 64 pairs). grid (4, 1024), 128 thr,
// 4 CTAs/SM. A single-buffered, B double-buffered, N=152, coalesced A-prep.
// ---------------------------------------------------------------------------
__global__ void __launch_bounds__(NTHR, 4) pair_mma_kernel(
    const float* __restrict__ sm, const float* __restrict__ b2,
    const float* __restrict__ W3, const float* __restrict__ b3,
    float* __restrict__ out)
{
    extern __shared__ char smem[];
    const uint32_t sb = smem_u32(smem);
    const int tid = threadIdx.x;
    const int i  = blockIdx.y;
    const int k0 = blockIdx.x * MT;

    if (i - WWIN + k0 + (MT - 1) < 0) {
        if (tid < MT) out[(size_t)i * OUTW + k0 + tid] = 0.f;
        return;
    }

    const int wid = tid >> 5, lid = tid & 31;
    const int wm = wid & 1, wn = wid >> 1;
    const int gq = lid >> 2, t = lid & 3;
    const bool trim = (wn == 1);

    int jrow[2][2];
    #pragma unroll
    for (int mi = 0; mi < 2; ++mi)
        #pragma unroll
        for (int h8 = 0; h8 < 2; ++h8) {
            int p = wm * 32 + mi * 16 + gq + h8 * 8;
            int j = i - WWIN + k0 + p;
            jrow[mi][h8] = min(max(j, 0), NN - 1);
        }

    float acc[2][10][4];
    {
        const float* giR = g_giT + i * HP;
        #pragma unroll
        for (int nt = 0; nt < 10; ++nt)
            #pragma unroll
            for (int par = 0; par < 2; ++par) {
                int col = wn * 80 + nt * 8 + 2 * t + par;
                float gic = giR[col];
                const float* gjc = g_gjT_T + col * NN;
                #pragma unroll
                for (int mi = 0; mi < 2; ++mi)
                    #pragma unroll
                    for (int h8 = 0; h8 < 2; ++h8)
                        acc[mi][nt][h8 * 2 + par] = gic + gjc[jrow[mi][h8]];
            }
    }

    const int mq = lid >> 3, rr = lid & 7;
    uint32_t aOff[2], bOff[5];
    #pragma unroll
    for (int mi = 0; mi < 2; ++mi)
        aOff[mi] = (uint32_t)((wm * 32 + mi * 16 + (mq & 1) * 8 + rr) * 144 + (mq >> 1) * 16);
    #pragma unroll
    for (int ntp = 0; ntp < 5; ++ntp) {
        int rowb = wn * 80 + (ntp * 2 + (mq >> 1)) * 8 + rr;
        if (rowb > 151) rowb = 151;
        bOff[ntp] = (uint32_t)(rowb * 144 + (mq & 1) * 16);
    }

    const int c8 = tid & 7;
    const int rA = tid >> 3;
    const __half* giBase = g_h + (size_t)i * DDIM;
    int jr[4];
    #pragma unroll
    for (int rd = 0; rd < 4; ++rd) {
        int p = rd * 16 + rA;
        jr[rd] = min(max(i - WWIN + k0 + p, 0), NN - 1);
    }

    {
        const char* src = (const char*)g_W1hi;
        for (int x = tid; x < TILE_B_U4; x += NTHR)
            cp16(sb + SB1 + x * 16, src + x * 16);
        CP_COMMIT();
        const uint4 gi16 = ((const uint4*)giBase)[c8];
        #pragma unroll
        for (int rd = 0; rd < 4; ++rd) {
            uint4 gj16 = ((const uint4*)(g_h + (size_t)jr[rd] * DDIM))[c8];
            *(uint4*)(smem + SA + (rd * 16 + rA) * 144 + c8 * 16) = hmul_u4(gi16, gj16);
        }
        CP_WAIT0();
        __syncthreads();
    }

    for (int kt = 0; kt < 8; ++kt) {
        if (kt < 7) {
            const char* src = (const char*)(g_W1hi + (kt + 1) * TILE_W_HALVES);
            uint32_t dstB = sb + (((kt + 1) & 1) ? SB0 : SB1);
            for (int x = tid; x < TILE_B_U4; x += NTHR)
                cp16(dstB + x * 16, src + x * 16);
            CP_COMMIT();
        } else {
            const char* src = (const char*)g_W2hi;
            for (int x = tid; x < TILE_B_U4; x += NTHR)
                cp16(sb + SB2 + x * 16, src + x * 16);
            CP_COMMIT();
        }

        const uint32_t bB = sb + ((kt & 1) ? SB0 : SB1);
        #pragma unroll
        for (int ks = 0; ks < 4; ++ks) {
            uint32_t ah0[4], ah1[4];
            ldsm4(ah0, sb + SA + aOff[0] + ks * 32);
            ldsm4(ah1, sb + SA + aOff[1] + ks * 32);
            #pragma unroll
            for (int ntp = 0; ntp < 5; ++ntp) {
                uint32_t bf[4];
                ldsm4(bf, bB + bOff[ntp] + ks * 32);
                mma16816(acc[0][2 * ntp],     ah0[0], ah0[1], ah0[2], ah0[3], bf[0], bf[1]);
                mma16816(acc[1][2 * ntp],     ah1[0], ah1[1], ah1[2], ah1[3], bf[0], bf[1]);
                if (ntp < 4 || !trim) {
                    mma16816(acc[0][2 * ntp + 1], ah0[0], ah0[1], ah0[2], ah0[3], bf[2], bf[3]);
                    mma16816(acc[1][2 * ntp + 1], ah1[0], ah1[1], ah1[2], ah1[3], bf[2], bf[3]);
                }
            }
        }
        __syncthreads();

        if (kt < 7) {
            const uint4 gi16 = ((const uint4*)(giBase + (kt + 1) * 64))[c8];
            #pragma unroll
            for (int rd = 0; rd < 4; ++rd) {
                uint4 gj16 = ((const uint4*)(g_h + (size_t)jr[rd] * DDIM + (kt + 1) * 64))[c8];
                *(uint4*)(smem + SA + (rd * 16 + rA) * 144 + c8 * 16) = hmul_u4(gi16, gj16);
            }
        }
        CP_WAIT0();
        __syncthreads();
    }

    {
        #pragma unroll
        for (int mi = 0; mi < 2; ++mi)
            #pragma unroll
            for (int h8 = 0; h8 < 2; ++h8) {
                int row = wm * 32 + mi * 16 + gq + h8 * 8;
                #pragma unroll
                for (int nt = 0; nt < 10; ++nt) {
                    int col = wn * 80 + nt * 8 + 2 * t;
                    float v0 = fmaxf(acc[mi][nt][h8 * 2 + 0], 0.f);
                    float v1 = fmaxf(acc[mi][nt][h8 * 2 + 1], 0.f);
                    __half2 h = __float22half2_rn(make_float2(v0, v1));
                    int tile = col >> 6;
                    uint32_t off = (uint32_t)(tile * 9216 + row * 144 + (col & 63) * 2);
                    *(uint32_t*)(smem + off) = *(uint32_t*)&h;
                }
            }
    }

    #pragma unroll
    for (int nt = 0; nt < 10; ++nt)
        #pragma unroll
        for (int par = 0; par < 2; ++par) {
            int col = wn * 80 + nt * 8 + 2 * t + par;
            float bv = (col < HDIM) ? b2[col] : 0.f;
            #pragma unroll
            for (int mi = 0; mi < 2; ++mi)
                #pragma unroll
                for (int h8 = 0; h8 < 2; ++h8)
                    acc[mi][nt][h8 * 2 + par] = bv;
        }
    __syncthreads();

    for (int kt2 = 0; kt2 < 3; ++kt2) {
        if (kt2 > 0) {
            const char* src = (const char*)(g_W2hi + kt2 * TILE_W_HALVES);
            for (int x = tid; x < TILE_B_U4; x += NTHR)
                cp16(sb + SB2 + x * 16, src + x * 16);
            CP_COMMIT();
            CP_WAIT0();
            __syncthreads();
        }
        const uint32_t aB2 = sb + kt2 * 9216;
        const int nks = (kt2 == 2) ? 2 : 4;
        for (int ks = 0; ks < nks; ++ks) {
            uint32_t af0[4], af1[4];
            ldsm4(af0, aB2 + aOff[0] + ks * 32);
            ldsm4(af1, aB2 + aOff[1] + ks * 32);
            #pragma unroll
            for (int ntp = 0; ntp < 5; ++ntp) {
                uint32_t bf[4];
                ldsm4(bf, sb + SB2 + bOff[ntp] + ks * 32);
                mma16816(acc[0][2 * ntp],     af0[0], af0[1], af0[2], af0[3], bf[0], bf[1]);
                mma16816(acc[1][2 * ntp],     af1[0], af1[1], af1[2], af1[3], bf[0], bf[1]);
                if (ntp < 4 || !trim) {
                    mma16816(acc[0][2 * ntp + 1], af0[0], af0[1], af0[2], af0[3], bf[2], bf[3]);
                    mma16816(acc[1][2 * ntp + 1], af1[0], af1[1], af1[2], af1[3], bf[2], bf[3]);
                }
            }
        }
        __syncthreads();
    }

    float rsum[2][2] = {{0.f, 0.f}, {0.f, 0.f}};
    #pragma unroll
    for (int nt = 0; nt < 10; ++nt)
        #pragma unroll
        for (int par = 0; par < 2; ++par) {
            int col = wn * 80 + nt * 8 + 2 * t + par;
            float w3 = (col < HDIM) ? W3[col] : 0.f;
            #pragma unroll
            for (int mi = 0; mi < 2; ++mi)
                #pragma unroll
                for (int h8 = 0; h8 < 2; ++h8)
                    rsum[mi][h8] += fmaxf(acc[mi][nt][h8 * 2 + par], 0.f) * w3;
        }
    #pragma unroll
    for (int mi = 0; mi < 2; ++mi)
        #pragma unroll
        for (int h8 = 0; h8 < 2; ++h8) {
            float v = rsum[mi][h8];
            v += __shfl_xor_sync(0xffffffffu, v, 1);
            v += __shfl_xor_sync(0xffffffffu, v, 2);
            rsum[mi][h8] = v;
        }

    float* sred = (float*)(smem + SRED);
    if (wn == 0 && t == 0) {
        #pragma unroll
        for (int mi = 0; mi < 2; ++mi)
            #pragma unroll
            for (int h8 = 0; h8 < 2; ++h8)
                sred[wm * 32 + mi * 16 + gq + h8 * 8] = rsum[mi][h8];
    }
    __syncthreads();
    if (wn == 1 && t == 0) {
        float smi = sm[i];
        float bb3 = b3[0];
        #pragma unroll
        for (int mi = 0; mi < 2; ++mi)
            #pragma unroll
            for (int h8 = 0; h8 < 2; ++h8) {
                int p = wm * 32 + mi * 16 + gq + h8 * 8;
                int k = k0 + p;
                int j = i - WWIN + k;
                float tot = rsum[mi][h8] + sred[p];
                if (k < WWIN) {
                    float val = 0.f;
                    if (j >= 0) val = tot + bb3 + smi + sm[j];
                    out[(size_t)i * OUTW + k] = val;
                } else if (k == WWIN) {
                    out[(size_t)i * OUTW + k] = 0.f;   // epsilon column
                }
            }
    }
}

// ---------------------------------------------------------------------------
extern "C" void kernel_launch(void* const* d_in, const int* in_sizes, int n_in,
                              void* d_out, int out_size)
{
    const float* g  = (const float*)d_in[0];
    const float* sm = (const float*)d_in[1];
    const float* W1 = (const float*)d_in[2];
    const float* b1 = (const float*)d_in[3];
    const float* W2 = (const float*)d_in[4];
    const float* b2 = (const float*)d_in[5];
    const float* W3 = (const float*)d_in[6];
    const float* b3 = (const float*)d_in[7];
    float* out = (float*)d_out;

    cudaFuncSetAttribute(pair_mma_kernel,
                         cudaFuncAttributeMaxDynamicSharedMemorySize, SMEM_TOTAL);
    cudaFuncSetAttribute(precompute_gt_mma,
                         cudaFuncAttributeMaxDynamicSharedMemorySize, GT_SMEM);

    dim3 wgrid(27, 8);
    precompute_w<<<wgrid, 256>>>(W1, W2);
    dim3 ggrid(2, 32);
    precompute_gt_mma<<<ggrid, 128, GT_SMEM>>>(g, b1);

    dim3 grid(4, NN);
    pair_mma_kernel<<<grid, NTHR, SMEM_TOTAL>>>(sm, b2, W3, b3, out);
}

// round 15
// speedup vs baseline: 1.1547x; 1.0620x over previous
#include <cuda_runtime.h>
#include <cuda_fp16.h>
#include <cstdint>

#define NN    1024
#define DDIM  512
#define HDIM  150
#define HP    160
#define WWIN  250
#define OUTW  251
#define NTHR  128
#define MT    64

// ---- dynamic SMEM byte offsets (main kernel) ----
#define SA    0
#define SB0   9216
#define SB1   31104
#define SB2   31104
#define SRED  52992
#define SMBAR 53248
#define SMEM_TOTAL 53504

#define BROWS 152
#define TILE_B_BYTES (BROWS * 144)      // 21888
#define TILE_B_U4    (TILE_B_BYTES/16)  // 1368
#define TILE_W_HALVES (BROWS * 72)      // 10944

// gt-mma kernel tiles: 160 rows, pitch 144
#define GT_TILE_HALVES (HP * 72)        // 11520
#define GT_TILE_BYTES  (HP * 144)       // 23040
#define GT_TILE_U4     (GT_TILE_BYTES/16) // 1440
#define GT_A_HI 0
#define GT_A_LO 4608
#define GT_B    9216
#define GT_SMEM 101376

// ---------------------------------------------------------------------------
// Device scratch
// ---------------------------------------------------------------------------
__device__ float g_giT[NN * HP];      // g@W1a + b1, [i][h], zero pad h>=150
__device__ float g_gjT_T[HP * NN];    // (g@W1b)^T, [h][i], zero pad
__device__ __align__(16) __half g_h[NN * DDIM];   // fp16 copy of g
__device__ __align__(16) __half g_W1hi[8 * TILE_W_HALVES];
__device__ __align__(16) __half g_W2hi[3 * TILE_W_HALVES];
__device__ __align__(16) __half g_Wahi[8 * GT_TILE_HALVES];
__device__ __align__(16) __half g_Walo[8 * GT_TILE_HALVES];
__device__ __align__(16) __half g_Wbhi[8 * GT_TILE_HALVES];
__device__ __align__(16) __half g_Wblo[8 * GT_TILE_HALVES];

// ---------------------------------------------------------------------------
// Helpers
// ---------------------------------------------------------------------------
__device__ __forceinline__ uint32_t smem_u32(const void* p) {
    uint32_t a;
    asm("{ .reg .u64 t; cvta.to.shared.u64 t, %1; cvt.u32.u64 %0, t; }"
        : "=r"(a) : "l"(p));
    return a;
}

__device__ __forceinline__ void cp16(uint32_t s, const void* g) {
    asm volatile("{\n\t.reg .u64 gp;\n\tcvta.to.global.u64 gp, %1;\n\t"
                 "cp.async.cg.shared.global [%0], [gp], 16;\n\t}"
                 :: "r"(s), "l"(g) : "memory");
}
#define CP_COMMIT() asm volatile("cp.async.commit_group;" ::: "memory")
#define CP_WAIT0()  asm volatile("cp.async.wait_group 0;" ::: "memory")

// Bulk copy global->shared with mbarrier completion (UBLKCP path)
__device__ __forceinline__ void bulk_cp(uint32_t dst, const void* src,
                                        uint32_t bytes, uint32_t mbar) {
    asm volatile("{\n\t.reg .u64 gp;\n\tcvta.to.global.u64 gp, %1;\n\t"
        "cp.async.bulk.shared::cluster.global.mbarrier::complete_tx::bytes "
        "[%0], [gp], %2, [%3];\n\t}"
        :: "r"(dst), "l"(src), "r"(bytes), "r"(mbar) : "memory");
}
#define MBAR_INIT(mb, c) \
    asm volatile("mbarrier.init.shared.b64 [%0], %1;" :: "r"(mb), "r"((uint32_t)(c)) : "memory")
#define MBAR_EXPECT(mb, bytes) \
    asm volatile("mbarrier.arrive.expect_tx.shared.b64 _, [%0], %1;" \
                 :: "r"(mb), "r"((uint32_t)(bytes)) : "memory")

__device__ __forceinline__ void mbar_wait(uint32_t mb, uint32_t parity) {
    uint32_t done;
    asm volatile("{\n\t.reg .pred p;\n\t"
                 "mbarrier.try_wait.parity.acquire.cta.shared::cta.b64 p, [%1], %2;\n\t"
                 "selp.b32 %0, 1, 0, p;\n\t}"
                 : "=r"(done) : "r"(mb), "r"(parity) : "memory");
    if (!done) {
        asm volatile("{\n\t.reg .pred P1;\n\t"
                     "WL_%=:\n\t"
                     "mbarrier.try_wait.parity.acquire.cta.shared::cta.b64 P1, [%0], %1, 0x989680;\n\t"
                     "@P1 bra.uni WD_%=;\n\t"
                     "bra.uni WL_%=;\n\t"
                     "WD_%=:\n\t}"
                     :: "r"(mb), "r"(parity) : "memory");
    }
}

__device__ __forceinline__ void ldsm4(uint32_t* r, uint32_t addr) {
    asm volatile("ldmatrix.sync.aligned.m8n8.x4.shared.b16 {%0,%1,%2,%3}, [%4];"
        : "=r"(r[0]), "=r"(r[1]), "=r"(r[2]), "=r"(r[3]) : "r"(addr));
}

__device__ __forceinline__ void mma16816(float* c,
    uint32_t a0, uint32_t a1, uint32_t a2, uint32_t a3,
    uint32_t b0, uint32_t b1)
{
    asm volatile(
        "mma.sync.aligned.m16n8k16.row.col.f32.f16.f16.f32 "
        "{%0,%1,%2,%3}, {%4,%5,%6,%7}, {%8,%9}, {%0,%1,%2,%3};"
        : "+f"(c[0]), "+f"(c[1]), "+f"(c[2]), "+f"(c[3])
        : "r"(a0), "r"(a1), "r"(a2), "r"(a3), "r"(b0), "r"(b1));
}

__device__ __forceinline__ uint4 hmul_u4(uint4 x, uint4 y) {
    __half2* xa = (__half2*)&x;
    __half2* ya = (__half2*)&y;
    uint4 r;
    __half2* ra = (__half2*)&r;
    ra[0] = __hmul2(xa[0], ya[0]);
    ra[1] = __hmul2(xa[1], ya[1]);
    ra[2] = __hmul2(xa[2], ya[2]);
    ra[3] = __hmul2(xa[3], ya[3]);
    return r;
}

// ---------------------------------------------------------------------------
// Kernel 1: weight tiles. grid (27, 8) x 256 thr (unchanged from R14).
// ---------------------------------------------------------------------------
__global__ void __launch_bounds__(256) precompute_w(
    const float* __restrict__ W1, const float* __restrict__ W2)
{
    const int bt = blockIdx.x;
    const int sl = blockIdx.y;
    const int tid = threadIdx.x;
    const int start = sl * 256 + tid;
    const int step  = 8 * 256;
    const float* W1c = W1 + 2 * DDIM * HDIM;
    const float* W1b = W1 + DDIM * HDIM;

    if (bt < 8) {
        __half* dhi = g_W1hi + bt * TILE_W_HALVES;
        for (int idx = start; idx < BROWS * 64; idx += step) {
            int n = idx >> 6, k = idx & 63;
            int d = bt * 64 + k;
            float val = (n < HDIM) ? W1c[d * HDIM + n] : 0.f;
            dhi[n * 72 + k] = __float2half_rn(val);
        }
    } else if (bt < 11) {
        const int kt = bt - 8;
        __half* dhi = g_W2hi + kt * TILE_W_HALVES;
        for (int idx = start; idx < BROWS * 64; idx += step) {
            int n = idx >> 6, k = idx & 63;
            int kg = kt * 64 + k;
            float val = (kg < HDIM && n < HDIM) ? W2[kg * HDIM + n] : 0.f;
            dhi[n * 72 + k] = __float2half_rn(val);
        }
    } else {
        const bool isA = (bt < 19);
        const int kt = isA ? (bt - 11) : (bt - 19);
        const float* src = isA ? W1 : W1b;
        __half* dhi = (isA ? g_Wahi : g_Wbhi) + kt * GT_TILE_HALVES;
        __half* dlo = (isA ? g_Walo : g_Wblo) + kt * GT_TILE_HALVES;
        for (int idx = start; idx < HP * 64; idx += step) {
            int n = idx >> 6, k = idx & 63;
            int d = kt * 64 + k;
            float val = (n < HDIM) ? src[d * HDIM + n] : 0.f;
            __half h = __float2half_rn(val);
            __half l = __float2half_rn(val - __half2float(h));
            dhi[n * 72 + k] = h;
            dlo[n * 72 + k] = l;
        }
    }
}

// ---------------------------------------------------------------------------
// Kernel 2: gt GEMM via fp16-split MMA (unchanged from R14).
// ---------------------------------------------------------------------------
__global__ void __launch_bounds__(128) precompute_gt_mma(
    const float* __restrict__ g, const float* __restrict__ b1)
{
    extern __shared__ char smem[];
    const uint32_t sb = smem_u32(smem);
    const int tid = threadIdx.x;
    const int gw = blockIdx.x;
    const int i0 = blockIdx.y * 32;

    const int wid = tid >> 5, lid = tid & 31;
    const int wm = wid & 1, wn = wid >> 1;
    const int gq = lid >> 2, t = lid & 3;
    const int mq = lid >> 3, rr = lid & 7;

    const __half* Whi = gw ? g_Wbhi : g_Wahi;
    const __half* Wlo = gw ? g_Wblo : g_Walo;

    float acc[10][4];
    #pragma unroll
    for (int nt = 0; nt < 10; ++nt)
        #pragma unroll
        for (int q = 0; q < 4; ++q) acc[nt][q] = 0.f;

    const uint32_t aOff = (uint32_t)((wm * 16 + (mq & 1) * 8 + rr) * 144 + (mq >> 1) * 16);
    uint32_t bOff[5];
    #pragma unroll
    for (int ntp = 0; ntp < 5; ++ntp) {
        int rowb = wn * 80 + (ntp * 2 + (mq >> 1)) * 8 + rr;
        bOff[ntp] = (uint32_t)(rowb * 144 + (mq & 1) * 16);
    }

    const int pA = tid >> 2;
    const int sA = tid & 3;
    const float4* gRow = (const float4*)(g + (size_t)(i0 + pA) * DDIM) + sA * 4;

    auto a_prep = [&](int kt) {
        float4 v[4];
        #pragma unroll
        for (int q = 0; q < 4; ++q) v[q] = gRow[kt * 16 + q];
        uint32_t hi[8], lo[8];
        #pragma unroll
        for (int q = 0; q < 4; ++q) {
            const float* f = (const float*)&v[q];
            __half2 h0 = __float22half2_rn(make_float2(f[0], f[1]));
            __half2 h1 = __float22half2_rn(make_float2(f[2], f[3]));
            float r0 = f[0] - __low2float(h0), r1 = f[1] - __high2float(h0);
            float r2 = f[2] - __low2float(h1), r3 = f[3] - __high2float(h1);
            __half2 l0 = __float22half2_rn(make_float2(r0, r1));
            __half2 l1 = __float22half2_rn(make_float2(r2, r3));
            hi[2 * q] = *(uint32_t*)&h0; hi[2 * q + 1] = *(uint32_t*)&h1;
            lo[2 * q] = *(uint32_t*)&l0; lo[2 * q + 1] = *(uint32_t*)&l1;
        }
        char* dh = smem + GT_A_HI + pA * 144 + sA * 32;
        char* dl = smem + GT_A_LO + pA * 144 + sA * 32;
        *(uint4*)(dh)      = make_uint4(hi[0], hi[1], hi[2], hi[3]);
        *(uint4*)(dh + 16) = make_uint4(hi[4], hi[5], hi[6], hi[7]);
        *(uint4*)(dl)      = make_uint4(lo[0], lo[1], lo[2], lo[3]);
        *(uint4*)(dl + 16) = make_uint4(lo[4], lo[5], lo[6], lo[7]);
        if (gw == 0) {
            uint4* gh = (uint4*)(g_h + (size_t)(i0 + pA) * DDIM + kt * 64 + sA * 16);
            gh[0] = make_uint4(hi[0], hi[1], hi[2], hi[3]);
            gh[1] = make_uint4(hi[4], hi[5], hi[6], hi[7]);
        }
    };

    {
        const char* shi = (const char*)Whi;
        const char* slo = (const char*)Wlo;
        for (int x = tid; x < GT_TILE_U4; x += 128) {
            cp16(sb + GT_B + x * 16, shi + x * 16);
            cp16(sb + GT_B + GT_TILE_BYTES + x * 16, slo + x * 16);
        }
        CP_COMMIT();
        a_prep(0);
        CP_WAIT0();
        __syncthreads();
    }

    for (int kt = 0; kt < 8; ++kt) {
        if (kt < 7) {
            const char* shi = (const char*)(Whi + (kt + 1) * GT_TILE_HALVES);
            const char* slo = (const char*)(Wlo + (kt + 1) * GT_TILE_HALVES);
            uint32_t dstB = sb + GT_B + (uint32_t)(((kt + 1) & 1) * 46080);
            for (int x = tid; x < GT_TILE_U4; x += 128) {
                cp16(dstB + x * 16, shi + x * 16);
                cp16(dstB + GT_TILE_BYTES + x * 16, slo + x * 16);
            }
            CP_COMMIT();
        }

        const uint32_t bB = sb + GT_B + (uint32_t)((kt & 1) * 46080);
        #pragma unroll
        for (int ks = 0; ks < 4; ++ks) {
            uint32_t ahi[4], alo[4];
            ldsm4(ahi, sb + GT_A_HI + aOff + ks * 32);
            ldsm4(alo, sb + GT_A_LO + aOff + ks * 32);
            #pragma unroll
            for (int ntp = 0; ntp < 5; ++ntp) {
                uint32_t bh[4], bl[4];
                ldsm4(bh, bB + bOff[ntp] + ks * 32);
                mma16816(acc[2 * ntp],     ahi[0], ahi[1], ahi[2], ahi[3], bh[0], bh[1]);
                mma16816(acc[2 * ntp + 1], ahi[0], ahi[1], ahi[2], ahi[3], bh[2], bh[3]);
                mma16816(acc[2 * ntp],     alo[0], alo[1], alo[2], alo[3], bh[0], bh[1]);
                mma16816(acc[2 * ntp + 1], alo[0], alo[1], alo[2], alo[3], bh[2], bh[3]);
                ldsm4(bl, bB + GT_TILE_BYTES + bOff[ntp] + ks * 32);
                mma16816(acc[2 * ntp],     ahi[0], ahi[1], ahi[2], ahi[3], bl[0], bl[1]);
                mma16816(acc[2 * ntp + 1], ahi[0], ahi[1], ahi[2], ahi[3], bl[2], bl[3]);
            }
        }
        __syncthreads();
        if (kt < 7) a_prep(kt + 1);
        CP_WAIT0();
        __syncthreads();
    }

    const int r0 = i0 + wm * 16 + gq;
    const int r1 = r0 + 8;
    #pragma unroll
    for (int nt = 0; nt < 10; ++nt)
        #pragma unroll
        for (int par = 0; par < 2; ++par) {
            int col = wn * 80 + nt * 8 + 2 * t + par;
            float v0 = acc[nt][par], v1 = acc[nt][2 + par];
            if (gw == 0) {
                float bb = (col < HDIM) ? b1[col] : 0.f;
                g_giT[r0 * HP + col] = v0 + bb;
                g_giT[r1 * HP + col] = v1 + bb;
            } else {
                g_gjT_T[col * NN + r0] = v0;
                g_gjT_T[col * NN + r1] = v1;
            }
        }
}

// ---------------------------------------------------------------------------
// Main kernel (R10 structure; B tiles via cp.async.bulk + mbarrier).
// ---------------------------------------------------------------------------
__global__ void __launch_bounds__(NTHR, 4) pair_mma_kernel(
    const float* __restrict__ sm, const float* __restrict__ b2,
    const float* __restrict__ W3, const float* __restrict__ b3,
    float* __restrict__ out)
{
    extern __shared__ char smem[];
    const uint32_t sb = smem_u32(smem);
    const int tid = threadIdx.x;
    const int i  = blockIdx.y;
    const int k0 = blockIdx.x * MT;

    if (i - WWIN + k0 + (MT - 1) < 0) {
        if (tid < MT) out[(size_t)i * OUTW + k0 + tid] = 0.f;
        return;
    }

    const uint32_t mbar = sb + SMBAR;
    uint32_t ph = 0;

    const int wid = tid >> 5, lid = tid & 31;
    const int wm = wid & 1, wn = wid >> 1;
    const int gq = lid >> 2, t = lid & 3;
    const bool trim = (wn == 1);

    int jrow[2][2];
    #pragma unroll
    for (int mi = 0; mi < 2; ++mi)
        #pragma unroll
        for (int h8 = 0; h8 < 2; ++h8) {
            int p = wm * 32 + mi * 16 + gq + h8 * 8;
            int j = i - WWIN + k0 + p;
            jrow[mi][h8] = min(max(j, 0), NN - 1);
        }

    float acc[2][10][4];
    {
        const float* giR = g_giT + i * HP;
        #pragma unroll
        for (int nt = 0; nt < 10; ++nt)
            #pragma unroll
            for (int par = 0; par < 2; ++par) {
                int col = wn * 80 + nt * 8 + 2 * t + par;
                float gic = giR[col];
                const float* gjc = g_gjT_T + col * NN;
                #pragma unroll
                for (int mi = 0; mi < 2; ++mi)
                    #pragma unroll
                    for (int h8 = 0; h8 < 2; ++h8)
                        acc[mi][nt][h8 * 2 + par] = gic + gjc[jrow[mi][h8]];
            }
    }

    const int mq = lid >> 3, rr = lid & 7;
    uint32_t aOff[2], bOff[5];
    #pragma unroll
    for (int mi = 0; mi < 2; ++mi)
        aOff[mi] = (uint32_t)((wm * 32 + mi * 16 + (mq & 1) * 8 + rr) * 144 + (mq >> 1) * 16);
    #pragma unroll
    for (int ntp = 0; ntp < 5; ++ntp) {
        int rowb = wn * 80 + (ntp * 2 + (mq >> 1)) * 8 + rr;
        if (rowb > 151) rowb = 151;
        bOff[ntp] = (uint32_t)(rowb * 144 + (mq & 1) * 16);
    }

    const int c8 = tid & 7;
    const int rA = tid >> 3;
    const __half* giBase = g_h + (size_t)i * DDIM;
    int jr[4];
    #pragma unroll
    for (int rd = 0; rd < 4; ++rd) {
        int p = rd * 16 + rA;
        jr[rd] = min(max(i - WWIN + k0 + p, 0), NN - 1);
    }

    // Prolog: init mbar, bulk B(0) -> SB1, A-prep(0)
    if (tid == 0) MBAR_INIT(mbar, 1);
    __syncthreads();
    if (tid == 0) {
        MBAR_EXPECT(mbar, TILE_B_BYTES);
        bulk_cp(sb + SB1, g_W1hi, TILE_B_BYTES, mbar);
    }
    {
        const uint4 gi16 = ((const uint4*)giBase)[c8];
        #pragma unroll
        for (int rd = 0; rd < 4; ++rd) {
            uint4 gj16 = ((const uint4*)(g_h + (size_t)jr[rd] * DDIM))[c8];
            *(uint4*)(smem + SA + (rd * 16 + rA) * 144 + c8 * 16) = hmul_u4(gi16, gj16);
        }
    }
    mbar_wait(mbar, ph); ph ^= 1;
    __syncthreads();

    for (int kt = 0; kt < 8; ++kt) {
        if (tid == 0) {
            const char* src = (kt < 7) ? (const char*)(g_W1hi + (kt + 1) * TILE_W_HALVES)
                                       : (const char*)g_W2hi;
            uint32_t dstB = (kt < 7) ? (sb + (((kt + 1) & 1) ? SB0 : SB1))
                                     : (sb + SB2);
            MBAR_EXPECT(mbar, TILE_B_BYTES);
            bulk_cp(dstB, src, TILE_B_BYTES, mbar);
        }

        const uint32_t bB = sb + ((kt & 1) ? SB0 : SB1);
        #pragma unroll
        for (int ks = 0; ks < 4; ++ks) {
            uint32_t ah0[4], ah1[4];
            ldsm4(ah0, sb + SA + aOff[0] + ks * 32);
            ldsm4(ah1, sb + SA + aOff[1] + ks * 32);
            #pragma unroll
            for (int ntp = 0; ntp < 5; ++ntp) {
                uint32_t bf[4];
                ldsm4(bf, bB + bOff[ntp] + ks * 32);
                mma16816(acc[0][2 * ntp],     ah0[0], ah0[1], ah0[2], ah0[3], bf[0], bf[1]);
                mma16816(acc[1][2 * ntp],     ah1[0], ah1[1], ah1[2], ah1[3], bf[0], bf[1]);
                if (ntp < 4 || !trim) {
                    mma16816(acc[0][2 * ntp + 1], ah0[0], ah0[1], ah0[2], ah0[3], bf[2], bf[3]);
                    mma16816(acc[1][2 * ntp + 1], ah1[0], ah1[1], ah1[2], ah1[3], bf[2], bf[3]);
                }
            }
        }
        __syncthreads();

        if (kt < 7) {
            const uint4 gi16 = ((const uint4*)(giBase + (kt + 1) * 64))[c8];
            #pragma unroll
            for (int rd = 0; rd < 4; ++rd) {
                uint4 gj16 = ((const uint4*)(g_h + (size_t)jr[rd] * DDIM + (kt + 1) * 64))[c8];
                *(uint4*)(smem + SA + (rd * 16 + rA) * 144 + c8 * 16) = hmul_u4(gi16, gj16);
            }
        }
        mbar_wait(mbar, ph); ph ^= 1;
        __syncthreads();
    }

    // h1 = relu(acc) -> SMEM (single fp16, 3 k-tiles)
    {
        #pragma unroll
        for (int mi = 0; mi < 2; ++mi)
            #pragma unroll
            for (int h8 = 0; h8 < 2; ++h8) {
                int row = wm * 32 + mi * 16 + gq + h8 * 8;
                #pragma unroll
                for (int nt = 0; nt < 10; ++nt) {
                    int col = wn * 80 + nt * 8 + 2 * t;
                    float v0 = fmaxf(acc[mi][nt][h8 * 2 + 0], 0.f);
                    float v1 = fmaxf(acc[mi][nt][h8 * 2 + 1], 0.f);
                    __half2 h = __float22half2_rn(make_float2(v0, v1));
                    int tile = col >> 6;
                    uint32_t off = (uint32_t)(tile * 9216 + row * 144 + (col & 63) * 2);
                    *(uint32_t*)(smem + off) = *(uint32_t*)&h;
                }
            }
    }

    #pragma unroll
    for (int nt = 0; nt < 10; ++nt)
        #pragma unroll
        for (int par = 0; par < 2; ++par) {
            int col = wn * 80 + nt * 8 + 2 * t + par;
            float bv = (col < HDIM) ? b2[col] : 0.f;
            #pragma unroll
            for (int mi = 0; mi < 2; ++mi)
                #pragma unroll
                for (int h8 = 0; h8 < 2; ++h8)
                    acc[mi][nt][h8 * 2 + par] = bv;
        }
    __syncthreads();

    // Stage 2: acc += relu(h1) @ W2 (fp16, K=160); W2 t0 already in SB2
    for (int kt2 = 0; kt2 < 3; ++kt2) {
        if (kt2 > 0) {
            if (tid == 0) {
                MBAR_EXPECT(mbar, TILE_B_BYTES);
                bulk_cp(sb + SB2, (const char*)(g_W2hi + kt2 * TILE_W_HALVES),
                        TILE_B_BYTES, mbar);
            }
            mbar_wait(mbar, ph); ph ^= 1;
            __syncthreads();
        }
        const uint32_t aB2 = sb + kt2 * 9216;
        const int nks = (kt2 == 2) ? 2 : 4;
        for (int ks = 0; ks < nks; ++ks) {
            uint32_t af0[4], af1[4];
            ldsm4(af0, aB2 + aOff[0] + ks * 32);
            ldsm4(af1, aB2 + aOff[1] + ks * 32);
            #pragma unroll
            for (int ntp = 0; ntp < 5; ++ntp) {
                uint32_t bf[4];
                ldsm4(bf, sb + SB2 + bOff[ntp] + ks * 32);
                mma16816(acc[0][2 * ntp],     af0[0], af0[1], af0[2], af0[3], bf[0], bf[1]);
                mma16816(acc[1][2 * ntp],     af1[0], af1[1], af1[2], af1[3], bf[0], bf[1]);
                if (ntp < 4 || !trim) {
                    mma16816(acc[0][2 * ntp + 1], af0[0], af0[1], af0[2], af0[3], bf[2], bf[3]);
                    mma16816(acc[1][2 * ntp + 1], af1[0], af1[1], af1[2], af1[3], bf[2], bf[3]);
                }
            }
        }
        __syncthreads();
    }

    // Epilogue
    float rsum[2][2] = {{0.f, 0.f}, {0.f, 0.f}};
    #pragma unroll
    for (int nt = 0; nt < 10; ++nt)
        #pragma unroll
        for (int par = 0; par < 2; ++par) {
            int col = wn * 80 + nt * 8 + 2 * t + par;
            float w3 = (col < HDIM) ? W3[col] : 0.f;
            #pragma unroll
            for (int mi = 0; mi < 2; ++mi)
                #pragma unroll
                for (int h8 = 0; h8 < 2; ++h8)
                    rsum[mi][h8] += fmaxf(acc[mi][nt][h8 * 2 + par], 0.f) * w3;
        }
    #pragma unroll
    for (int mi = 0; mi < 2; ++mi)
        #pragma unroll
        for (int h8 = 0; h8 < 2; ++h8) {
            float v = rsum[mi][h8];
            v += __shfl_xor_sync(0xffffffffu, v, 1);
            v += __shfl_xor_sync(0xffffffffu, v, 2);
            rsum[mi][h8] = v;
        }

    float* sred = (float*)(smem + SRED);
    if (wn == 0 && t == 0) {
        #pragma unroll
        for (int mi = 0; mi < 2; ++mi)
            #pragma unroll
            for (int h8 = 0; h8 < 2; ++h8)
                sred[wm * 32 + mi * 16 + gq + h8 * 8] = rsum[mi][h8];
    }
    __syncthreads();
    if (wn == 1 && t == 0) {
        float smi = sm[i];
        float bb3 = b3[0];
        #pragma unroll
        for (int mi = 0; mi < 2; ++mi)
            #pragma unroll
            for (int h8 = 0; h8 < 2; ++h8) {
                int p = wm * 32 + mi * 16 + gq + h8 * 8;
                int k = k0 + p;
                int j = i - WWIN + k;
                float tot = rsum[mi][h8] + sred[p];
                if (k < WWIN) {
                    float val = 0.f;
                    if (j >= 0) val = tot + bb3 + smi + sm[j];
                    out[(size_t)i * OUTW + k] = val;
                } else if (k == WWIN) {
                    out[(size_t)i * OUTW + k] = 0.f;   // epsilon column
                }
            }
    }
}

// ---------------------------------------------------------------------------
extern "C" void kernel_launch(void* const* d_in, const int* in_sizes, int n_in,
                              void* d_out, int out_size)
{
    const float* g  = (const float*)d_in[0];
    const float* sm = (const float*)d_in[1];
    const float* W1 = (const float*)d_in[2];
    const float* b1 = (const float*)d_in[3];
    const float* W2 = (const float*)d_in[4];
    const float* b2 = (const float*)d_in[5];
    const float* W3 = (const float*)d_in[6];
    const float* b3 = (const float*)d_in[7];
    float* out = (float*)d_out;

    cudaFuncSetAttribute(pair_mma_kernel,
                         cudaFuncAttributeMaxDynamicSharedMemorySize, SMEM_TOTAL);
    cudaFuncSetAttribute(precompute_gt_mma,
                         cudaFuncAttributeMaxDynamicSharedMemorySize, GT_SMEM);

    dim3 wgrid(27, 8);
    precompute_w<<<wgrid, 256>>>(W1, W2);
    dim3 ggrid(2, 32);
    precompute_gt_mma<<<ggrid, 128, GT_SMEM>>>(g, b1);

    dim3 grid(4, NN);
    pair_mma_kernel<<<grid, NTHR, SMEM_TOTAL>>>(sm, b2, W3, b3, out);
}

// round 16
// speedup vs baseline: 1.1561x; 1.0012x over previous
#include <cuda_runtime.h>
#include <cuda_fp16.h>
#include <cstdint>

#define NN    1024
#define DDIM  512
#define HDIM  150
#define HP    160
#define WWIN  250
#define OUTW  251
#define NTHR  128
#define MT    64

// ---- dynamic SMEM byte offsets (main kernel) ----
#define SA    0
#define SB0   9216
#define SB1   31104
#define SB2   31104
#define SRED  52992
#define SMBAR 53248
#define SMEM_TOTAL 53504

#define BROWS 152
#define TILE_B_BYTES (BROWS * 144)      // 21888
#define TILE_W_HALVES (BROWS * 72)      // 10944

// gt-mma kernel tiles: 160 rows, pitch 144
#define GT_TILE_HALVES (HP * 72)        // 11520
#define GT_TILE_BYTES  (HP * 144)       // 23040
#define GT_A_HI 0
#define GT_A_LO 4608
#define GT_B    9216
#define GT_MBAR 101376
#define GT_SMEM 101632

// ---------------------------------------------------------------------------
// Device scratch
// ---------------------------------------------------------------------------
__device__ float g_giT[NN * HP];      // g@W1a + b1, [i][h], zero pad h>=150
__device__ float g_gjT_T[HP * NN];    // (g@W1b)^T, [h][i], zero pad
__device__ __align__(16) __half g_h[NN * DDIM];   // fp16 copy of g
__device__ __align__(16) __half g_W1hi[8 * TILE_W_HALVES];
__device__ __align__(16) __half g_W2hi[3 * TILE_W_HALVES];
__device__ __align__(16) __half g_Wahi[8 * GT_TILE_HALVES];
__device__ __align__(16) __half g_Walo[8 * GT_TILE_HALVES];
__device__ __align__(16) __half g_Wbhi[8 * GT_TILE_HALVES];
__device__ __align__(16) __half g_Wblo[8 * GT_TILE_HALVES];

// ---------------------------------------------------------------------------
// Helpers
// ---------------------------------------------------------------------------
__device__ __forceinline__ uint32_t smem_u32(const void* p) {
    uint32_t a;
    asm("{ .reg .u64 t; cvta.to.shared.u64 t, %1; cvt.u32.u64 %0, t; }"
        : "=r"(a) : "l"(p));
    return a;
}

__device__ __forceinline__ void bulk_cp(uint32_t dst, const void* src,
                                        uint32_t bytes, uint32_t mbar) {
    asm volatile("{\n\t.reg .u64 gp;\n\tcvta.to.global.u64 gp, %1;\n\t"
        "cp.async.bulk.shared::cluster.global.mbarrier::complete_tx::bytes "
        "[%0], [gp], %2, [%3];\n\t}"
        :: "r"(dst), "l"(src), "r"(bytes), "r"(mbar) : "memory");
}
#define MBAR_INIT(mb, c) \
    asm volatile("mbarrier.init.shared.b64 [%0], %1;" :: "r"(mb), "r"((uint32_t)(c)) : "memory")
#define MBAR_EXPECT(mb, bytes) \
    asm volatile("mbarrier.arrive.expect_tx.shared.b64 _, [%0], %1;" \
                 :: "r"(mb), "r"((uint32_t)(bytes)) : "memory")

__device__ __forceinline__ void mbar_wait(uint32_t mb, uint32_t parity) {
    uint32_t done;
    asm volatile("{\n\t.reg .pred p;\n\t"
                 "mbarrier.try_wait.parity.acquire.cta.shared::cta.b64 p, [%1], %2;\n\t"
                 "selp.b32 %0, 1, 0, p;\n\t}"
                 : "=r"(done) : "r"(mb), "r"(parity) : "memory");
    if (!done) {
        asm volatile("{\n\t.reg .pred P1;\n\t"
                     "WL_%=:\n\t"
                     "mbarrier.try_wait.parity.acquire.cta.shared::cta.b64 P1, [%0], %1, 0x989680;\n\t"
                     "@P1 bra.uni WD_%=;\n\t"
                     "bra.uni WL_%=;\n\t"
                     "WD_%=:\n\t}"
                     :: "r"(mb), "r"(parity) : "memory");
    }
}

__device__ __forceinline__ void ldsm4(uint32_t* r, uint32_t addr) {
    asm volatile("ldmatrix.sync.aligned.m8n8.x4.shared.b16 {%0,%1,%2,%3}, [%4];"
        : "=r"(r[0]), "=r"(r[1]), "=r"(r[2]), "=r"(r[3]) : "r"(addr));
}

__device__ __forceinline__ void mma16816(float* c,
    uint32_t a0, uint32_t a1, uint32_t a2, uint32_t a3,
    uint32_t b0, uint32_t b1)
{
    asm volatile(
        "mma.sync.aligned.m16n8k16.row.col.f32.f16.f16.f32 "
        "{%0,%1,%2,%3}, {%4,%5,%6,%7}, {%8,%9}, {%0,%1,%2,%3};"
        : "+f"(c[0]), "+f"(c[1]), "+f"(c[2]), "+f"(c[3])
        : "r"(a0), "r"(a1), "r"(a2), "r"(a3), "r"(b0), "r"(b1));
}

__device__ __forceinline__ uint4 hmul_u4(uint4 x, uint4 y) {
    __half2* xa = (__half2*)&x;
    __half2* ya = (__half2*)&y;
    uint4 r;
    __half2* ra = (__half2*)&r;
    ra[0] = __hmul2(xa[0], ya[0]);
    ra[1] = __hmul2(xa[1], ya[1]);
    ra[2] = __hmul2(xa[2], ya[2]);
    ra[3] = __hmul2(xa[3], ya[3]);
    return r;
}

// ---------------------------------------------------------------------------
// Kernel 1: W1a/W1b hi+lo split tiles only (gt_mma's inputs).
// grid (16, 8) x 256 thr: bt 0..7 = W1a, 8..15 = W1b.
// ---------------------------------------------------------------------------
__global__ void __launch_bounds__(256) precompute_w(
    const float* __restrict__ W1)
{
    const int bt = blockIdx.x;
    const int sl = blockIdx.y;
    const int tid = threadIdx.x;
    const int start = sl * 256 + tid;
    const int step  = 8 * 256;
    const float* W1b = W1 + DDIM * HDIM;

    const bool isA = (bt < 8);
    const int kt = isA ? bt : (bt - 8);
    const float* src = isA ? W1 : W1b;
    __half* dhi = (isA ? g_Wahi : g_Wbhi) + kt * GT_TILE_HALVES;
    __half* dlo = (isA ? g_Walo : g_Wblo) + kt * GT_TILE_HALVES;
    for (int idx = start; idx < HP * 64; idx += step) {
        int n = idx >> 6, k = idx & 63;
        int d = kt * 64 + k;
        float val = (n < HDIM) ? src[d * HDIM + n] : 0.f;
        __half h = __float2half_rn(val);
        __half l = __float2half_rn(val - __half2float(h));
        dhi[n * 72 + k] = h;
        dlo[n * 72 + k] = l;
    }
}

// ---------------------------------------------------------------------------
// Kernel 2: blocks 0..63 = gt GEMM (fp16-split MMA, bulk B copies);
//           blocks 64..96 = W1c/W2 main-kernel tiles (11 tiles x 3 slices).
// ---------------------------------------------------------------------------
__global__ void __launch_bounds__(128) precompute_gt_mma(
    const float* __restrict__ g, const float* __restrict__ b1,
    const float* __restrict__ W1, const float* __restrict__ W2)
{
    const int tid = threadIdx.x;

    if (blockIdx.x >= 64) {
        // ---- W1c / W2 tile prep (for main kernel) ----
        const int wt = blockIdx.x - 64;       // 0..32
        const int bt = wt / 3;                // tile 0..10
        const int sl = wt % 3;                // slice 0..2
        const float* W1c = W1 + 2 * DDIM * HDIM;
        const int start = sl * 128 + tid;
        const int step  = 3 * 128;
        if (bt < 8) {
            __half* dhi = g_W1hi + bt * TILE_W_HALVES;
            for (int idx = start; idx < BROWS * 64; idx += step) {
                int n = idx >> 6, k = idx & 63;
                int d = bt * 64 + k;
                float val = (n < HDIM) ? W1c[d * HDIM + n] : 0.f;
                dhi[n * 72 + k] = __float2half_rn(val);
            }
        } else {
            const int kt = bt - 8;
            __half* dhi = g_W2hi + kt * TILE_W_HALVES;
            for (int idx = start; idx < BROWS * 64; idx += step) {
                int n = idx >> 6, k = idx & 63;
                int kg = kt * 64 + k;
                float val = (kg < HDIM && n < HDIM) ? W2[kg * HDIM + n] : 0.f;
                dhi[n * 72 + k] = __float2half_rn(val);
            }
        }
        return;
    }

    // ---- gt GEMM path ----
    extern __shared__ char smem[];
    const uint32_t sb = smem_u32(smem);
    const int gw = blockIdx.x & 1;
    const int i0 = (blockIdx.x >> 1) * 32;
    const uint32_t mbar = sb + GT_MBAR;
    uint32_t ph = 0;

    const int wid = tid >> 5, lid = tid & 31;
    const int wm = wid & 1, wn = wid >> 1;
    const int gq = lid >> 2, t = lid & 3;
    const int mq = lid >> 3, rr = lid & 7;

    const __half* Whi = gw ? g_Wbhi : g_Wahi;
    const __half* Wlo = gw ? g_Wblo : g_Walo;

    float acc[10][4];
    #pragma unroll
    for (int nt = 0; nt < 10; ++nt)
        #pragma unroll
        for (int q = 0; q < 4; ++q) acc[nt][q] = 0.f;

    const uint32_t aOff = (uint32_t)((wm * 16 + (mq & 1) * 8 + rr) * 144 + (mq >> 1) * 16);
    uint32_t bOff[5];
    #pragma unroll
    for (int ntp = 0; ntp < 5; ++ntp) {
        int rowb = wn * 80 + (ntp * 2 + (mq >> 1)) * 8 + rr;
        bOff[ntp] = (uint32_t)(rowb * 144 + (mq & 1) * 16);
    }

    const int pA = tid >> 2;
    const int sA = tid & 3;
    const float4* gRow = (const float4*)(g + (size_t)(i0 + pA) * DDIM) + sA * 4;

    auto a_prep = [&](int kt) {
        float4 v[4];
        #pragma unroll
        for (int q = 0; q < 4; ++q) v[q] = gRow[kt * 16 + q];
        uint32_t hi[8], lo[8];
        #pragma unroll
        for (int q = 0; q < 4; ++q) {
            const float* f = (const float*)&v[q];
            __half2 h0 = __float22half2_rn(make_float2(f[0], f[1]));
            __half2 h1 = __float22half2_rn(make_float2(f[2], f[3]));
            float r0 = f[0] - __low2float(h0), r1 = f[1] - __high2float(h0);
            float r2 = f[2] - __low2float(h1), r3 = f[3] - __high2float(h1);
            __half2 l0 = __float22half2_rn(make_float2(r0, r1));
            __half2 l1 = __float22half2_rn(make_float2(r2, r3));
            hi[2 * q] = *(uint32_t*)&h0; hi[2 * q + 1] = *(uint32_t*)&h1;
            lo[2 * q] = *(uint32_t*)&l0; lo[2 * q + 1] = *(uint32_t*)&l1;
        }
        char* dh = smem + GT_A_HI + pA * 144 + sA * 32;
        char* dl = smem + GT_A_LO + pA * 144 + sA * 32;
        *(uint4*)(dh)      = make_uint4(hi[0], hi[1], hi[2], hi[3]);
        *(uint4*)(dh + 16) = make_uint4(hi[4], hi[5], hi[6], hi[7]);
        *(uint4*)(dl)      = make_uint4(lo[0], lo[1], lo[2], lo[3]);
        *(uint4*)(dl + 16) = make_uint4(lo[4], lo[5], lo[6], lo[7]);
        if (gw == 0) {
            uint4* gh = (uint4*)(g_h + (size_t)(i0 + pA) * DDIM + kt * 64 + sA * 16);
            gh[0] = make_uint4(hi[0], hi[1], hi[2], hi[3]);
            gh[1] = make_uint4(hi[4], hi[5], hi[6], hi[7]);
        }
    };

    // Prolog: mbar init, bulk B(0) -> buf0, A(0)
    if (tid == 0) MBAR_INIT(mbar, 1);
    __syncthreads();
    if (tid == 0) {
        MBAR_EXPECT(mbar, 2 * GT_TILE_BYTES);
        bulk_cp(sb + GT_B, Whi, GT_TILE_BYTES, mbar);
        bulk_cp(sb + GT_B + GT_TILE_BYTES, Wlo, GT_TILE_BYTES, mbar);
    }
    a_prep(0);
    mbar_wait(mbar, ph); ph ^= 1;
    __syncthreads();

    for (int kt = 0; kt < 8; ++kt) {
        if (kt < 7 && tid == 0) {
            uint32_t dstB = sb + GT_B + (uint32_t)(((kt + 1) & 1) * 46080);
            MBAR_EXPECT(mbar, 2 * GT_TILE_BYTES);
            bulk_cp(dstB, Whi + (kt + 1) * GT_TILE_HALVES, GT_TILE_BYTES, mbar);
            bulk_cp(dstB + GT_TILE_BYTES, Wlo + (kt + 1) * GT_TILE_HALVES,
                    GT_TILE_BYTES, mbar);
        }

        const uint32_t bB = sb + GT_B + (uint32_t)((kt & 1) * 46080);
        #pragma unroll
        for (int ks = 0; ks < 4; ++ks) {
            uint32_t ahi[4], alo[4];
            ldsm4(ahi, sb + GT_A_HI + aOff + ks * 32);
            ldsm4(alo, sb + GT_A_LO + aOff + ks * 32);
            #pragma unroll
            for (int ntp = 0; ntp < 5; ++ntp) {
                uint32_t bh[4], bl[4];
                ldsm4(bh, bB + bOff[ntp] + ks * 32);
                mma16816(acc[2 * ntp],     ahi[0], ahi[1], ahi[2], ahi[3], bh[0], bh[1]);
                mma16816(acc[2 * ntp + 1], ahi[0], ahi[1], ahi[2], ahi[3], bh[2], bh[3]);
                mma16816(acc[2 * ntp],     alo[0], alo[1], alo[2], alo[3], bh[0], bh[1]);
                mma16816(acc[2 * ntp + 1], alo[0], alo[1], alo[2], alo[3], bh[2], bh[3]);
                ldsm4(bl, bB + GT_TILE_BYTES + bOff[ntp] + ks * 32);
                mma16816(acc[2 * ntp],     ahi[0], ahi[1], ahi[2], ahi[3], bl[0], bl[1]);
                mma16816(acc[2 * ntp + 1], ahi[0], ahi[1], ahi[2], ahi[3], bl[2], bl[3]);
            }
        }
        __syncthreads();
        if (kt < 7) {
            a_prep(kt + 1);
            mbar_wait(mbar, ph); ph ^= 1;
        }
        __syncthreads();
    }

    const int r0 = i0 + wm * 16 + gq;
    const int r1 = r0 + 8;
    #pragma unroll
    for (int nt = 0; nt < 10; ++nt)
        #pragma unroll
        for (int par = 0; par < 2; ++par) {
            int col = wn * 80 + nt * 8 + 2 * t + par;
            float v0 = acc[nt][par], v1 = acc[nt][2 + par];
            if (gw == 0) {
                float bb = (col < HDIM) ? b1[col] : 0.f;
                g_giT[r0 * HP + col] = v0 + bb;
                g_giT[r1 * HP + col] = v1 + bb;
            } else {
                g_gjT_T[col * NN + r0] = v0;
                g_gjT_T[col * NN + r1] = v1;
            }
        }
}

// ---------------------------------------------------------------------------
// Main kernel (R15 verbatim): B tiles via cp.async.bulk + mbarrier.
// ---------------------------------------------------------------------------
__global__ void __launch_bounds__(NTHR, 4) pair_mma_kernel(
    const float* __restrict__ sm, const float* __restrict__ b2,
    const float* __restrict__ W3, const float* __restrict__ b3,
    float* __restrict__ out)
{
    extern __shared__ char smem[];
    const uint32_t sb = smem_u32(smem);
    const int tid = threadIdx.x;
    const int i  = blockIdx.y;
    const int k0 = blockIdx.x * MT;

    if (i - WWIN + k0 + (MT - 1) < 0) {
        if (tid < MT) out[(size_t)i * OUTW + k0 + tid] = 0.f;
        return;
    }

    const uint32_t mbar = sb + SMBAR;
    uint32_t ph = 0;

    const int wid = tid >> 5, lid = tid & 31;
    const int wm = wid & 1, wn = wid >> 1;
    const int gq = lid >> 2, t = lid & 3;
    const bool trim = (wn == 1);

    int jrow[2][2];
    #pragma unroll
    for (int mi = 0; mi < 2; ++mi)
        #pragma unroll
        for (int h8 = 0; h8 < 2; ++h8) {
            int p = wm * 32 + mi * 16 + gq + h8 * 8;
            int j = i - WWIN + k0 + p;
            jrow[mi][h8] = min(max(j, 0), NN - 1);
        }

    float acc[2][10][4];
    {
        const float* giR = g_giT + i * HP;
        #pragma unroll
        for (int nt = 0; nt < 10; ++nt)
            #pragma unroll
            for (int par = 0; par < 2; ++par) {
                int col = wn * 80 + nt * 8 + 2 * t + par;
                float gic = giR[col];
                const float* gjc = g_gjT_T + col * NN;
                #pragma unroll
                for (int mi = 0; mi < 2; ++mi)
                    #pragma unroll
                    for (int h8 = 0; h8 < 2; ++h8)
                        acc[mi][nt][h8 * 2 + par] = gic + gjc[jrow[mi][h8]];
            }
    }

    const int mq = lid >> 3, rr = lid & 7;
    uint32_t aOff[2], bOff[5];
    #pragma unroll
    for (int mi = 0; mi < 2; ++mi)
        aOff[mi] = (uint32_t)((wm * 32 + mi * 16 + (mq & 1) * 8 + rr) * 144 + (mq >> 1) * 16);
    #pragma unroll
    for (int ntp = 0; ntp < 5; ++ntp) {
        int rowb = wn * 80 + (ntp * 2 + (mq >> 1)) * 8 + rr;
        if (rowb > 151) rowb = 151;
        bOff[ntp] = (uint32_t)(rowb * 144 + (mq & 1) * 16);
    }

    const int c8 = tid & 7;
    const int rA = tid >> 3;
    const __half* giBase = g_h + (size_t)i * DDIM;
    int jr[4];
    #pragma unroll
    for (int rd = 0; rd < 4; ++rd) {
        int p = rd * 16 + rA;
        jr[rd] = min(max(i - WWIN + k0 + p, 0), NN - 1);
    }

    if (tid == 0) MBAR_INIT(mbar, 1);
    __syncthreads();
    if (tid == 0) {
        MBAR_EXPECT(mbar, TILE_B_BYTES);
        bulk_cp(sb + SB1, g_W1hi, TILE_B_BYTES, mbar);
    }
    {
        const uint4 gi16 = ((const uint4*)giBase)[c8];
        #pragma unroll
        for (int rd = 0; rd < 4; ++rd) {
            uint4 gj16 = ((const uint4*)(g_h + (size_t)jr[rd] * DDIM))[c8];
            *(uint4*)(smem + SA + (rd * 16 + rA) * 144 + c8 * 16) = hmul_u4(gi16, gj16);
        }
    }
    mbar_wait(mbar, ph); ph ^= 1;
    __syncthreads();

    for (int kt = 0; kt < 8; ++kt) {
        if (tid == 0) {
            const char* src = (kt < 7) ? (const char*)(g_W1hi + (kt + 1) * TILE_W_HALVES)
                                       : (const char*)g_W2hi;
            uint32_t dstB = (kt < 7) ? (sb + (((kt + 1) & 1) ? SB0 : SB1))
                                     : (sb + SB2);
            MBAR_EXPECT(mbar, TILE_B_BYTES);
            bulk_cp(dstB, src, TILE_B_BYTES, mbar);
        }

        const uint32_t bB = sb + ((kt & 1) ? SB0 : SB1);
        #pragma unroll
        for (int ks = 0; ks < 4; ++ks) {
            uint32_t ah0[4], ah1[4];
            ldsm4(ah0, sb + SA + aOff[0] + ks * 32);
            ldsm4(ah1, sb + SA + aOff[1] + ks * 32);
            #pragma unroll
            for (int ntp = 0; ntp < 5; ++ntp) {
                uint32_t bf[4];
                ldsm4(bf, bB + bOff[ntp] + ks * 32);
                mma16816(acc[0][2 * ntp],     ah0[0], ah0[1], ah0[2], ah0[3], bf[0], bf[1]);
                mma16816(acc[1][2 * ntp],     ah1[0], ah1[1], ah1[2], ah1[3], bf[0], bf[1]);
                if (ntp < 4 || !trim) {
                    mma16816(acc[0][2 * ntp + 1], ah0[0], ah0[1], ah0[2], ah0[3], bf[2], bf[3]);
                    mma16816(acc[1][2 * ntp + 1], ah1[0], ah1[1], ah1[2], ah1[3], bf[2], bf[3]);
                }
            }
        }
        __syncthreads();

        if (kt < 7) {
            const uint4 gi16 = ((const uint4*)(giBase + (kt + 1) * 64))[c8];
            #pragma unroll
            for (int rd = 0; rd < 4; ++rd) {
                uint4 gj16 = ((const uint4*)(g_h + (size_t)jr[rd] * DDIM + (kt + 1) * 64))[c8];
                *(uint4*)(smem + SA + (rd * 16 + rA) * 144 + c8 * 16) = hmul_u4(gi16, gj16);
            }
        }
        mbar_wait(mbar, ph); ph ^= 1;
        __syncthreads();
    }

    {
        #pragma unroll
        for (int mi = 0; mi < 2; ++mi)
            #pragma unroll
            for (int h8 = 0; h8 < 2; ++h8) {
                int row = wm * 32 + mi * 16 + gq + h8 * 8;
                #pragma unroll
                for (int nt = 0; nt < 10; ++nt) {
                    int col = wn * 80 + nt * 8 + 2 * t;
                    float v0 = fmaxf(acc[mi][nt][h8 * 2 + 0], 0.f);
                    float v1 = fmaxf(acc[mi][nt][h8 * 2 + 1], 0.f);
                    __half2 h = __float22half2_rn(make_float2(v0, v1));
                    int tile = col >> 6;
                    uint32_t off = (uint32_t)(tile * 9216 + row * 144 + (col & 63) * 2);
                    *(uint32_t*)(smem + off) = *(uint32_t*)&h;
                }
            }
    }

    #pragma unroll
    for (int nt = 0; nt < 10; ++nt)
        #pragma unroll
        for (int par = 0; par < 2; ++par) {
            int col = wn * 80 + nt * 8 + 2 * t + par;
            float bv = (col < HDIM) ? b2[col] : 0.f;
            #pragma unroll
            for (int mi = 0; mi < 2; ++mi)
                #pragma unroll
                for (int h8 = 0; h8 < 2; ++h8)
                    acc[mi][nt][h8 * 2 + par] = bv;
        }
    __syncthreads();

    for (int kt2 = 0; kt2 < 3; ++kt2) {
        if (kt2 > 0) {
            if (tid == 0) {
                MBAR_EXPECT(mbar, TILE_B_BYTES);
                bulk_cp(sb + SB2, (const char*)(g_W2hi + kt2 * TILE_W_HALVES),
                        TILE_B_BYTES, mbar);
            }
            mbar_wait(mbar, ph); ph ^= 1;
            __syncthreads();
        }
        const uint32_t aB2 = sb + kt2 * 9216;
        const int nks = (kt2 == 2) ? 2 : 4;
        for (int ks = 0; ks < nks; ++ks) {
            uint32_t af0[4], af1[4];
            ldsm4(af0, aB2 + aOff[0] + ks * 32);
            ldsm4(af1, aB2 + aOff[1] + ks * 32);
            #pragma unroll
            for (int ntp = 0; ntp < 5; ++ntp) {
                uint32_t bf[4];
                ldsm4(bf, sb + SB2 + bOff[ntp] + ks * 32);
                mma16816(acc[0][2 * ntp],     af0[0], af0[1], af0[2], af0[3], bf[0], bf[1]);
                mma16816(acc[1][2 * ntp],     af1[0], af1[1], af1[2], af1[3], bf[0], bf[1]);
                if (ntp < 4 || !trim) {
                    mma16816(acc[0][2 * ntp + 1], af0[0], af0[1], af0[2], af0[3], bf[2], bf[3]);
                    mma16816(acc[1][2 * ntp + 1], af1[0], af1[1], af1[2], af1[3], bf[2], bf[3]);
                }
            }
        }
        __syncthreads();
    }

    float rsum[2][2] = {{0.f, 0.f}, {0.f, 0.f}};
    #pragma unroll
    for (int nt = 0; nt < 10; ++nt)
        #pragma unroll
        for (int par = 0; par < 2; ++par) {
            int col = wn * 80 + nt * 8 + 2 * t + par;
            float w3 = (col < HDIM) ? W3[col] : 0.f;
            #pragma unroll
            for (int mi = 0; mi < 2; ++mi)
                #pragma unroll
                for (int h8 = 0; h8 < 2; ++h8)
                    rsum[mi][h8] += fmaxf(acc[mi][nt][h8 * 2 + par], 0.f) * w3;
        }
    #pragma unroll
    for (int mi = 0; mi < 2; ++mi)
        #pragma unroll
        for (int h8 = 0; h8 < 2; ++h8) {
            float v = rsum[mi][h8];
            v += __shfl_xor_sync(0xffffffffu, v, 1);
            v += __shfl_xor_sync(0xffffffffu, v, 2);
            rsum[mi][h8] = v;
        }

    float* sred = (float*)(smem + SRED);
    if (wn == 0 && t == 0) {
        #pragma unroll
        for (int mi = 0; mi < 2; ++mi)
            #pragma unroll
            for (int h8 = 0; h8 < 2; ++h8)
                sred[wm * 32 + mi * 16 + gq + h8 * 8] = rsum[mi][h8];
    }
    __syncthreads();
    if (wn == 1 && t == 0) {
        float smi = sm[i];
        float bb3 = b3[0];
        #pragma unroll
        for (int mi = 0; mi < 2; ++mi)
            #pragma unroll
            for (int h8 = 0; h8 < 2; ++h8) {
                int p = wm * 32 + mi * 16 + gq + h8 * 8;
                int k = k0 + p;
                int j = i - WWIN + k;
                float tot = rsum[mi][h8] + sred[p];
                if (k < WWIN) {
                    float val = 0.f;
                    if (j >= 0) val = tot + bb3 + smi + sm[j];
                    out[(size_t)i * OUTW + k] = val;
                } else if (k == WWIN) {
                    out[(size_t)i * OUTW + k] = 0.f;   // epsilon column
                }
            }
    }
}

// ---------------------------------------------------------------------------
extern "C" void kernel_launch(void* const* d_in, const int* in_sizes, int n_in,
                              void* d_out, int out_size)
{
    const float* g  = (const float*)d_in[0];
    const float* sm = (const float*)d_in[1];
    const float* W1 = (const float*)d_in[2];
    const float* b1 = (const float*)d_in[3];
    const float* W2 = (const float*)d_in[4];
    const float* b2 = (const float*)d_in[5];
    const float* W3 = (const float*)d_in[6];
    const float* b3 = (const float*)d_in[7];
    float* out = (float*)d_out;

    cudaFuncSetAttribute(pair_mma_kernel,
                         cudaFuncAttributeMaxDynamicSharedMemorySize, SMEM_TOTAL);
    cudaFuncSetAttribute(precompute_gt_mma,
                         cudaFuncAttributeMaxDynamicSharedMemorySize, GT_SMEM);

    dim3 wgrid(16, 8);
    precompute_w<<<wgrid, 256>>>(W1);
    precompute_gt_mma<<<97, 128, GT_SMEM>>>(g, b1, W1, W2);

    dim3 grid(4, NN);
    pair_mma_kernel<<<grid, NTHR, SMEM_TOTAL>>>(sm, b2, W3, b3, out);
}